// round 1
// baseline (speedup 1.0000x reference)
#include <cuda_runtime.h>

#define Bz 32
#define Vz 21
#define Dz 512
#define Pz 64
#define INz 32768
#define OUTz 96
#define Ez 8
#define Rz 8
#define Hz 256
#define NROWS (Bz*Vz)          /* 672 */
#define NCOLS (OUTz + Ez*Rz)   /* 160 */
#define NCOLP 161              /* padded smem stride, coprime banks */
#define SPLITK 16
#define KC (INz/SPLITK)        /* 2048 */
#define KK 16
#define MT 32
#define NSTEP (KC/KK)          /* 128 */
#define SCALE 2.0f             /* alpha/rank = 16/8 */

// ---------------- device scratch (no allocations allowed) ----------------
__device__ float g_pooled[Bz*Dz];
__device__ float g_w[Bz*Ez];                       // top-2 weights * SCALE, 0 elsewhere
__device__ float g_part[SPLITK*NROWS*NCOLS];       // split-K partials (~6.9 MB)

// ---------------- 1) pooled[b,d] = mean over v,p of x ----------------
__global__ void pool_kernel(const float* __restrict__ x) {
    int warp = (blockIdx.x * blockDim.x + threadIdx.x) >> 5;
    int lane = threadIdx.x & 31;
    if (warp >= Bz * Dz) return;
    int b = warp / Dz, d = warp % Dz;
    const float* base = x + ((size_t)(b * Vz) * Dz + d) * Pz;
    float s = 0.f;
    #pragma unroll
    for (int v = 0; v < Vz; v++) {
        const float2* p2 = (const float2*)(base + (size_t)v * Dz * Pz);
        float2 val = p2[lane];   // 32 lanes x float2 = 64 contiguous floats (p dim)
        s += val.x + val.y;
    }
    #pragma unroll
    for (int o = 16; o; o >>= 1) s += __shfl_xor_sync(0xffffffffu, s, o);
    if (lane == 0) g_pooled[warp] = s * (1.0f / (Vz * Pz));
}

// ---------------- 2) router: MLP -> softmax -> top-2 -> scaled weights ----
__global__ void router_kernel(const float* __restrict__ W1, const float* __restrict__ b1,
                              const float* __restrict__ W2, const float* __restrict__ b2,
                              float* __restrict__ out_probs) {
    __shared__ float sp[Dz];
    __shared__ float sh[Hz];
    __shared__ float sl[Ez];
    int b = blockIdx.x, t = threadIdx.x;
    for (int i = t; i < Dz; i += 256) sp[i] = g_pooled[b * Dz + i];
    __syncthreads();
    if (t < Hz) {
        float acc = b1[t];
        const float* w = W1 + (size_t)t * Dz;
        #pragma unroll 8
        for (int k = 0; k < Dz; k++) acc = fmaf(sp[k], w[k], acc);
        sh[t] = fmaxf(acc, 0.f);
    }
    __syncthreads();
    if (t < Ez) {
        float acc = b2[t];
        const float* w = W2 + (size_t)t * Hz;
        #pragma unroll 8
        for (int k = 0; k < Hz; k++) acc = fmaf(sh[k], w[k], acc);
        sl[t] = acc;
    }
    __syncthreads();
    if (t == 0) {
        float mx = -1e30f;
        #pragma unroll
        for (int e = 0; e < Ez; e++) mx = fmaxf(mx, sl[e]);
        float pr[Ez]; float se = 0.f;
        #pragma unroll
        for (int e = 0; e < Ez; e++) { pr[e] = expf(sl[e] - mx); se += pr[e]; }
        float inv = 1.0f / se;
        #pragma unroll
        for (int e = 0; e < Ez; e++) { pr[e] *= inv; out_probs[b * Ez + e] = pr[e]; }
        // top-2 (ties -> lower index, matching lax.top_k)
        int i0 = 0;
        #pragma unroll
        for (int e = 1; e < Ez; e++) if (pr[e] > pr[i0]) i0 = e;
        int i1 = (i0 == 0) ? 1 : 0;
        #pragma unroll
        for (int e = 0; e < Ez; e++) if (e != i0 && pr[e] > pr[i1]) i1 = e;
        float s2 = pr[i0] + pr[i1];
        if (s2 < 1e-6f) s2 = 1e-6f;
        float inv2 = SCALE / s2;
        #pragma unroll
        for (int e = 0; e < Ez; e++) g_w[b * Ez + e] = 0.f;
        g_w[b * Ez + i0] = pr[i0] * inv2;
        g_w[b * Ez + i1] = pr[i1] * inv2;
    }
}

// ---------------- 3) main split-K SGEMM: [672,32768] @ [32768,160] ----------
// B-matrix rows: 0..95 = W_base, 96..159 = lora_A (all experts, flattened [64, IN])
__global__ __launch_bounds__(256, 2)
void gemm_kernel(const float* __restrict__ x,
                 const float* __restrict__ Wb,
                 const float* __restrict__ lA) {
    __shared__ float As[2][MT][KK + 1];    // [buf][m][kk], pad avoids store conflicts
    __shared__ float Bs[2][KK][NCOLP];     // [buf][kk][n], stride 161 -> stride-5 reads conflict-free
    const int t  = threadIdx.x;
    const int m0 = blockIdx.x * MT;
    const int k0 = blockIdx.y * KC;

    const int rg = t >> 5;   // 0..7 : rows rg*4 .. rg*4+3 (uniform per warp -> LDS broadcast)
    const int cg = t & 31;   // 0..31: cols cg*5 .. cg*5+4

    // A loader: row ar (0..31), kk=(t&7)*2 via float2
    const int ar = t >> 3;
    const int ak = (t & 7) * 2;
    const float* aptr = x + (size_t)(m0 + ar) * INz + k0 + ak;

    // B loader: kk = t&15, n = (t>>4) + j*16
    const int bk  = t & 15;
    const int bn0 = t >> 4;
    const float* bptr[10];
    #pragma unroll
    for (int j = 0; j < 10; j++) {
        int n = bn0 + j * 16;
        const float* row = (n < OUTz) ? (Wb + (size_t)n * INz)
                                      : (lA + (size_t)(n - OUTz) * INz);
        bptr[j] = row + k0 + bk;
    }

    float acc[4][5];
    #pragma unroll
    for (int i = 0; i < 4; i++)
        #pragma unroll
        for (int j = 0; j < 5; j++) acc[i][j] = 0.f;

    // prologue: stage step 0
    float2 aReg = *(const float2*)aptr;
    float  bReg[10];
    #pragma unroll
    for (int j = 0; j < 10; j++) bReg[j] = bptr[j][0];
    As[0][ar][ak]     = aReg.x;
    As[0][ar][ak + 1] = aReg.y;
    #pragma unroll
    for (int j = 0; j < 10; j++) Bs[0][bk][bn0 + j * 16] = bReg[j];
    __syncthreads();

    for (int s = 0; s < NSTEP; s++) {
        const int cur = s & 1;
        const int nxt = cur ^ 1;
        if (s + 1 < NSTEP) {
            const int off = (s + 1) * KK;
            aReg = *(const float2*)(aptr + off);
            #pragma unroll
            for (int j = 0; j < 10; j++) bReg[j] = bptr[j][off];
        }
        #pragma unroll
        for (int kk = 0; kk < KK; kk++) {
            float a0 = As[cur][rg * 4 + 0][kk];
            float a1 = As[cur][rg * 4 + 1][kk];
            float a2 = As[cur][rg * 4 + 2][kk];
            float a3 = As[cur][rg * 4 + 3][kk];
            float b0 = Bs[cur][kk][cg * 5 + 0];
            float b1 = Bs[cur][kk][cg * 5 + 1];
            float b2 = Bs[cur][kk][cg * 5 + 2];
            float b3 = Bs[cur][kk][cg * 5 + 3];
            float b4 = Bs[cur][kk][cg * 5 + 4];
            acc[0][0] = fmaf(a0, b0, acc[0][0]); acc[0][1] = fmaf(a0, b1, acc[0][1]);
            acc[0][2] = fmaf(a0, b2, acc[0][2]); acc[0][3] = fmaf(a0, b3, acc[0][3]);
            acc[0][4] = fmaf(a0, b4, acc[0][4]);
            acc[1][0] = fmaf(a1, b0, acc[1][0]); acc[1][1] = fmaf(a1, b1, acc[1][1]);
            acc[1][2] = fmaf(a1, b2, acc[1][2]); acc[1][3] = fmaf(a1, b3, acc[1][3]);
            acc[1][4] = fmaf(a1, b4, acc[1][4]);
            acc[2][0] = fmaf(a2, b0, acc[2][0]); acc[2][1] = fmaf(a2, b1, acc[2][1]);
            acc[2][2] = fmaf(a2, b2, acc[2][2]); acc[2][3] = fmaf(a2, b3, acc[2][3]);
            acc[2][4] = fmaf(a2, b4, acc[2][4]);
            acc[3][0] = fmaf(a3, b0, acc[3][0]); acc[3][1] = fmaf(a3, b1, acc[3][1]);
            acc[3][2] = fmaf(a3, b2, acc[3][2]); acc[3][3] = fmaf(a3, b3, acc[3][3]);
            acc[3][4] = fmaf(a3, b4, acc[3][4]);
        }
        if (s + 1 < NSTEP) {
            As[nxt][ar][ak]     = aReg.x;
            As[nxt][ar][ak + 1] = aReg.y;
            #pragma unroll
            for (int j = 0; j < 10; j++) Bs[nxt][bk][bn0 + j * 16] = bReg[j];
        }
        __syncthreads();
    }

    float* outp = g_part + ((size_t)blockIdx.y * NROWS + m0) * NCOLS;
    #pragma unroll
    for (int i = 0; i < 4; i++)
        #pragma unroll
        for (int j = 0; j < 5; j++)
            outp[(rg * 4 + i) * NCOLS + cg * 5 + j] = acc[i][j];
}

// ---------------- 4) split-K reduce + bias + top-2 LoRA combine -------------
__global__ void reduce_kernel(const float* __restrict__ b_base,
                              const float* __restrict__ lB,   // [E][OUT][R]
                              float* __restrict__ out) {
    const int row = blockIdx.x;        // 0..671
    const int t   = threadIdx.x;       // 0..159
    const int b   = row / Vz;
    __shared__ float temp[Ez * Rz];
    float v = 0.f;
    #pragma unroll
    for (int s = 0; s < SPLITK; s++)
        v += g_part[((size_t)s * NROWS + row) * NCOLS + t];
    if (t >= OUTz) temp[t - OUTz] = v;
    __syncthreads();
    if (t < OUTz) {
        float o = b_base[t] + v;
        #pragma unroll
        for (int e = 0; e < Ez; e++) {
            float w = g_w[b * Ez + e];
            if (w != 0.f) {
                float d = 0.f;
                #pragma unroll
                for (int r = 0; r < Rz; r++)
                    d = fmaf(lB[((size_t)e * OUTz + t) * Rz + r], temp[e * Rz + r], d);
                o = fmaf(w, d, o);
            }
        }
        out[(size_t)row * OUTz + t] = o;
    }
}

// ---------------- launch ----------------
extern "C" void kernel_launch(void* const* d_in, const int* in_sizes, int n_in,
                              void* d_out, int out_size) {
    const float* x   = (const float*)d_in[0];
    const float* Wb  = (const float*)d_in[1];
    const float* bb  = (const float*)d_in[2];
    const float* W1  = (const float*)d_in[3];
    const float* b1v = (const float*)d_in[4];
    const float* W2  = (const float*)d_in[5];
    const float* b2v = (const float*)d_in[6];
    const float* lA  = (const float*)d_in[7];
    const float* lB  = (const float*)d_in[8];
    float* out = (float*)d_out;

    // output layout: [672*96] fused head output, then [32*8] router probs
    float* out_probs = out + (size_t)NROWS * OUTz;

    pool_kernel<<<(Bz * Dz) / 8, 256>>>(x);
    router_kernel<<<Bz, 256>>>(W1, b1v, W2, b2v, out_probs);
    gemm_kernel<<<dim3(21, SPLITK), 256>>>(x, Wb, lA);
    reduce_kernel<<<NROWS, NCOLS>>>(bb, lB, out);
    (void)in_sizes; (void)n_in; (void)out_size;
}

// round 3
// speedup vs baseline: 1.7002x; 1.7002x over previous
#include <cuda_runtime.h>
#include <cuda_bf16.h>
#include <cstdint>

#define Bz 32
#define Vz 21
#define Dz 512
#define Pz 64
#define INz 32768
#define OUTz 96
#define Ez 8
#define Rz 8
#define Hz 256
#define NROWS (Bz*Vz)          /* 672 */
#define NCOLS (OUTz + Ez*Rz)   /* 160 */
#define SPLITK 16
#define KC (INz/SPLITK)        /* 2048 */
#define SCALE 2.0f

// GEMM tiling
#define MT 64
#define KT 32
#define NSTEP (KC/KT)          /* 64 */
// smem layout (bytes): rows padded to 80B (32 bf16 + 16B pad) -> ldmatrix conflict-free
#define AH_OFF 0
#define AL_OFF 5120            /* 64*80 */
#define BH_OFF 10240
#define BL_OFF 23040           /* +160*80 */
#define STAGE  35840
#define SM_TOTAL (2*STAGE)     /* 71680 */

// ---------------- device scratch ----------------
__device__ float g_pooled[Bz*Dz];
__device__ float g_w[Bz*Ez];
__device__ float g_part[SPLITK*NROWS*NCOLS];
__device__ __nv_bfloat16 g_Bh[(size_t)NCOLS*INz];   // B-matrix hi plane [160][32768]
__device__ __nv_bfloat16 g_Bl[(size_t)NCOLS*INz];   // lo plane

// ---------------- PTX helpers (compute_80-safe) ----------------
__device__ __forceinline__ uint32_t smem_u32(const void* p) {
    uint32_t a;
    asm("{ .reg .u64 t; cvta.to.shared.u64 t, %1; cvt.u32.u64 %0, t; }" : "=r"(a) : "l"(p));
    return a;
}
#define CP16(dst, src)  asm volatile("cp.async.cg.shared.global [%0], [%1], 16;" :: "r"(dst), "l"(src) : "memory")
#define CP_COMMIT()     asm volatile("cp.async.commit_group;" ::: "memory")
#define CP_WAIT0()      asm volatile("cp.async.wait_group 0;" ::: "memory")
#define LDSM4(r0,r1,r2,r3,addr) \
    asm volatile("ldmatrix.sync.aligned.m8n8.x4.shared.b16 {%0,%1,%2,%3}, [%4];" \
        : "=r"(r0),"=r"(r1),"=r"(r2),"=r"(r3) : "r"(addr))
#define MMA(d, a, b0, b1) \
    asm volatile("mma.sync.aligned.m16n8k16.row.col.f32.bf16.bf16.f32 " \
        "{%0,%1,%2,%3},{%4,%5,%6,%7},{%8,%9},{%0,%1,%2,%3};" \
        : "+f"((d)[0]),"+f"((d)[1]),"+f"((d)[2]),"+f"((d)[3]) \
        : "r"((a)[0]),"r"((a)[1]),"r"((a)[2]),"r"((a)[3]), "r"(b0),"r"(b1))

__device__ __forceinline__ void cvt_hilo(float4 f, uint2& h, uint2& l) {
    __nv_bfloat162 h01 = __floats2bfloat162_rn(f.x, f.y);
    __nv_bfloat162 h23 = __floats2bfloat162_rn(f.z, f.w);
    float rx = f.x - __bfloat162float(h01.x);
    float ry = f.y - __bfloat162float(h01.y);
    float rz = f.z - __bfloat162float(h23.x);
    float rw = f.w - __bfloat162float(h23.y);
    __nv_bfloat162 l01 = __floats2bfloat162_rn(rx, ry);
    __nv_bfloat162 l23 = __floats2bfloat162_rn(rz, rw);
    h.x = reinterpret_cast<uint32_t&>(h01);
    h.y = reinterpret_cast<uint32_t&>(h23);
    l.x = reinterpret_cast<uint32_t&>(l01);
    l.y = reinterpret_cast<uint32_t&>(l23);
}

// ---------------- 0) pre-convert B-matrix (W_base ++ lora_A) to bf16 hi/lo ----
__global__ void bprep_kernel(const float* __restrict__ Wb, const float* __restrict__ lA) {
    int idx = blockIdx.x * 256 + threadIdx.x;           // float4 index
    if (idx >= NCOLS * (INz / 4)) return;
    int row = idx / (INz / 4);
    int c   = idx % (INz / 4);
    const float* src = (row < OUTz ? Wb + (size_t)row * INz
                                   : lA + (size_t)(row - OUTz) * INz) + c * 4;
    float4 f = *(const float4*)src;
    uint2 h, l; cvt_hilo(f, h, l);
    ((uint2*)g_Bh)[idx] = h;
    ((uint2*)g_Bl)[idx] = l;
}

// ---------------- 1) pool ----------------
__global__ void pool_kernel(const float* __restrict__ x) {
    int warp = (blockIdx.x * blockDim.x + threadIdx.x) >> 5;
    int lane = threadIdx.x & 31;
    if (warp >= Bz * Dz) return;
    int b = warp / Dz, d = warp % Dz;
    const float* base = x + ((size_t)(b * Vz) * Dz + d) * Pz;
    float s = 0.f;
    #pragma unroll
    for (int v = 0; v < Vz; v++) {
        float2 val = ((const float2*)(base + (size_t)v * Dz * Pz))[lane];
        s += val.x + val.y;
    }
    #pragma unroll
    for (int o = 16; o; o >>= 1) s += __shfl_xor_sync(0xffffffffu, s, o);
    if (lane == 0) g_pooled[warp] = s * (1.0f / (Vz * Pz));
}

// ---------------- 2) router ----------------
__global__ void router_kernel(const float* __restrict__ W1, const float* __restrict__ b1,
                              const float* __restrict__ W2, const float* __restrict__ b2,
                              float* __restrict__ out_probs) {
    __shared__ float sp[Dz];
    __shared__ float sh[Hz];
    __shared__ float sl[Ez];
    int b = blockIdx.x, t = threadIdx.x;
    for (int i = t; i < Dz; i += 256) sp[i] = g_pooled[b * Dz + i];
    __syncthreads();
    if (t < Hz) {
        float acc = b1[t];
        const float* w = W1 + (size_t)t * Dz;
        #pragma unroll 8
        for (int k = 0; k < Dz; k++) acc = fmaf(sp[k], w[k], acc);
        sh[t] = fmaxf(acc, 0.f);
    }
    __syncthreads();
    if (t < Ez) {
        float acc = b2[t];
        const float* w = W2 + (size_t)t * Hz;
        #pragma unroll 8
        for (int k = 0; k < Hz; k++) acc = fmaf(sh[k], w[k], acc);
        sl[t] = acc;
    }
    __syncthreads();
    if (t == 0) {
        float mx = -1e30f;
        #pragma unroll
        for (int e = 0; e < Ez; e++) mx = fmaxf(mx, sl[e]);
        float pr[Ez]; float se = 0.f;
        #pragma unroll
        for (int e = 0; e < Ez; e++) { pr[e] = expf(sl[e] - mx); se += pr[e]; }
        float inv = 1.0f / se;
        #pragma unroll
        for (int e = 0; e < Ez; e++) { pr[e] *= inv; out_probs[b * Ez + e] = pr[e]; }
        int i0 = 0;
        #pragma unroll
        for (int e = 1; e < Ez; e++) if (pr[e] > pr[i0]) i0 = e;
        int i1 = (i0 == 0) ? 1 : 0;
        #pragma unroll
        for (int e = 0; e < Ez; e++) if (e != i0 && pr[e] > pr[i1]) i1 = e;
        float s2 = pr[i0] + pr[i1];
        if (s2 < 1e-6f) s2 = 1e-6f;
        float inv2 = SCALE / s2;
        #pragma unroll
        for (int e = 0; e < Ez; e++) g_w[b * Ez + e] = 0.f;
        g_w[b * Ez + i0] = pr[i0] * inv2;
        g_w[b * Ez + i1] = pr[i1] * inv2;
    }
}

// ---------------- 3) mma.sync split-K GEMM (bf16 hi/lo, fp32 acc) ----------------
// grid (11, SPLITK), 256 thr (8 warps: 4 along M x 2 along N)
__global__ __launch_bounds__(256, 2)
void gemm_mma_kernel(const float* __restrict__ x) {
    extern __shared__ char smem[];
    const uint32_t sb = smem_u32(smem);
    const int t = threadIdx.x;
    const int lane = t & 31;
    const int wid = t >> 5;
    const int wm = wid & 3;         // m-tile: rows wm*16..+15
    const int wn = wid >> 2;        // n-half: cols wn*80..+79
    const int m0 = blockIdx.x * MT;
    const int k0 = blockIdx.y * KC;

    // A loader: 2 float4 per thread per stage
    const float* aptr[2]; uint32_t asts[2]; bool aval[2];
    #pragma unroll
    for (int j = 0; j < 2; j++) {
        int idx = t + j * 256;
        int arow = idx >> 3, ac4 = idx & 7;
        aval[j] = (m0 + arow) < NROWS;
        aptr[j] = x + (size_t)(aval[j] ? m0 + arow : 0) * INz + k0 + ac4 * 4;
        asts[j] = (uint32_t)(arow * 80 + ac4 * 8);
    }
    // B loader: 5 x 16B cp.async per thread per stage (hi plane idx<640, then lo)
    const __nv_bfloat16* bsrc[5]; uint32_t bsts[5];
    #pragma unroll
    for (int j = 0; j < 5; j++) {
        int idx = t + j * 256;
        int plane = idx >= 640;
        int i2 = idx - plane * 640;
        int brow = i2 >> 2, bc = i2 & 3;
        bsrc[j] = (plane ? g_Bl : g_Bh) + (size_t)brow * INz + k0 + bc * 8;
        bsts[j] = (uint32_t)((plane ? BL_OFF : BH_OFF) + brow * 80 + bc * 16);
    }

    // ldmatrix lane addresses
    const uint32_t a_lane = (uint32_t)((wm * 16 + (lane & 15)) * 80 + (lane >> 4) * 16);
    const int q = (lane >> 3) & 3;
    const uint32_t b_lane = (uint32_t)(((q >> 1) * 8 + (lane & 7)) * 80 + (q & 1) * 16
                                       + wn * 80 * 80 + BH_OFF);

    float acc[10][4];
    #pragma unroll
    for (int j = 0; j < 10; j++)
        #pragma unroll
        for (int i = 0; i < 4; i++) acc[j][i] = 0.f;

    // prologue: stage 0
    float4 areg[2];
    #pragma unroll
    for (int j = 0; j < 2; j++)
        areg[j] = aval[j] ? *(const float4*)aptr[j] : make_float4(0.f, 0.f, 0.f, 0.f);
    #pragma unroll
    for (int j = 0; j < 5; j++) CP16(sb + bsts[j], bsrc[j]);
    CP_COMMIT();

    for (int s = 0; s < NSTEP; s++) {
        const uint32_t base = sb + (uint32_t)(s & 1) * STAGE;
        // convert + store A hi/lo for stage s
        #pragma unroll
        for (int j = 0; j < 2; j++) {
            uint2 h, l; cvt_hilo(areg[j], h, l);
            *(uint2*)(smem + (base - sb) + AH_OFF + asts[j]) = h;
            *(uint2*)(smem + (base - sb) + AL_OFF + asts[j]) = l;
        }
        CP_WAIT0();
        __syncthreads();
        if (s + 1 < NSTEP) {
            const int koff = (s + 1) * KT;
            #pragma unroll
            for (int j = 0; j < 2; j++)
                areg[j] = aval[j] ? *(const float4*)(aptr[j] + koff)
                                  : make_float4(0.f, 0.f, 0.f, 0.f);
            const uint32_t nbase = sb + (uint32_t)((s + 1) & 1) * STAGE;
            #pragma unroll
            for (int j = 0; j < 5; j++) CP16(nbase + bsts[j], bsrc[j] + koff);
            CP_COMMIT();
        }
        // compute
        #pragma unroll
        for (int kk = 0; kk < 2; kk++) {
            uint32_t ah[4], al[4];
            LDSM4(ah[0], ah[1], ah[2], ah[3], base + AH_OFF + a_lane + kk * 32);
            LDSM4(al[0], al[1], al[2], al[3], base + AL_OFF + a_lane + kk * 32);
            #pragma unroll
            for (int jp = 0; jp < 5; jp++) {
                uint32_t bh[4], bl[4];
                const uint32_t ba = base + b_lane + jp * 1280 + kk * 32;
                LDSM4(bh[0], bh[1], bh[2], bh[3], ba);
                LDSM4(bl[0], bl[1], bl[2], bl[3], ba + (BL_OFF - BH_OFF));
                MMA(acc[jp * 2 + 0], ah, bh[0], bh[1]);
                MMA(acc[jp * 2 + 0], ah, bl[0], bl[1]);
                MMA(acc[jp * 2 + 0], al, bh[0], bh[1]);
                MMA(acc[jp * 2 + 1], ah, bh[2], bh[3]);
                MMA(acc[jp * 2 + 1], ah, bl[2], bl[3]);
                MMA(acc[jp * 2 + 1], al, bh[2], bh[3]);
            }
        }
        __syncthreads();
    }

    // epilogue: write split-K partials
    float* outp = g_part + (size_t)blockIdx.y * NROWS * NCOLS;
    const int r0 = m0 + wm * 16 + (lane >> 2);
    const int c0 = wn * 80 + (lane & 3) * 2;
    #pragma unroll
    for (int j = 0; j < 10; j++) {
        int col = c0 + j * 8;
        if (r0 < NROWS)
            *(float2*)(outp + (size_t)r0 * NCOLS + col) = make_float2(acc[j][0], acc[j][1]);
        if (r0 + 8 < NROWS)
            *(float2*)(outp + (size_t)(r0 + 8) * NCOLS + col) = make_float2(acc[j][2], acc[j][3]);
    }
}

// ---------------- 4) split-K reduce + bias + top-2 LoRA combine ----------------
__global__ void reduce_kernel(const float* __restrict__ b_base,
                              const float* __restrict__ lB,
                              float* __restrict__ out) {
    const int row = blockIdx.x;
    const int t = threadIdx.x;
    const int b = row / Vz;
    __shared__ float temp[Ez * Rz];
    float v = 0.f;
    #pragma unroll
    for (int s = 0; s < SPLITK; s++)
        v += g_part[((size_t)s * NROWS + row) * NCOLS + t];
    if (t >= OUTz) temp[t - OUTz] = v;
    __syncthreads();
    if (t < OUTz) {
        float o = b_base[t] + v;
        #pragma unroll
        for (int e = 0; e < Ez; e++) {
            float w = g_w[b * Ez + e];
            if (w != 0.f) {
                float d = 0.f;
                #pragma unroll
                for (int r = 0; r < Rz; r++)
                    d = fmaf(lB[((size_t)e * OUTz + t) * Rz + r], temp[e * Rz + r], d);
                o = fmaf(w, d, o);
            }
        }
        out[(size_t)row * OUTz + t] = o;
    }
}

// ---------------- launch ----------------
extern "C" void kernel_launch(void* const* d_in, const int* in_sizes, int n_in,
                              void* d_out, int out_size) {
    const float* x   = (const float*)d_in[0];
    const float* Wb  = (const float*)d_in[1];
    const float* bb  = (const float*)d_in[2];
    const float* W1  = (const float*)d_in[3];
    const float* b1v = (const float*)d_in[4];
    const float* W2  = (const float*)d_in[5];
    const float* b2v = (const float*)d_in[6];
    const float* lA  = (const float*)d_in[7];
    const float* lB  = (const float*)d_in[8];
    float* out = (float*)d_out;
    float* out_probs = out + (size_t)NROWS * OUTz;

    cudaFuncSetAttribute(gemm_mma_kernel, cudaFuncAttributeMaxDynamicSharedMemorySize, SM_TOTAL);

    bprep_kernel<<<(NCOLS * (INz / 4) + 255) / 256, 256>>>(Wb, lA);
    pool_kernel<<<(Bz * Dz) / 8, 256>>>(x);
    router_kernel<<<Bz, 256>>>(W1, b1v, W2, b2v, out_probs);
    gemm_mma_kernel<<<dim3(11, SPLITK), 256, SM_TOTAL>>>(x);
    reduce_kernel<<<NROWS, NCOLS>>>(bb, lB, out);
    (void)in_sizes; (void)n_in; (void)out_size;
}

// round 4
// speedup vs baseline: 1.9827x; 1.1661x over previous
#include <cuda_runtime.h>
#include <cuda_bf16.h>
#include <cstdint>

#define Bz 32
#define Vz 21
#define Dz 512
#define Pz 64
#define INz 32768
#define OUTz 96
#define Ez 8
#define Rz 8
#define Hz 256
#define NROWS (Bz*Vz)          /* 672 */
#define NCOLS (OUTz + Ez*Rz)   /* 160 */
#define SPLITK 64
#define KC (INz/SPLITK)        /* 512 */
#define SCALE 2.0f

// GEMM tiling
#define MT 64
#define KT 32
#define NSTEP (KC/KT)          /* 16 */
// smem layout (bytes): rows padded to 80B (32 bf16 + 16B pad) -> ldmatrix conflict-free
#define AH_OFF 0
#define AL_OFF 5120            /* 64*80 */
#define BH_OFF 10240
#define BL_OFF 23040           /* +160*80 */
#define STAGE  35840
#define SM_TOTAL (2*STAGE)     /* 71680 */

// ---------------- device scratch ----------------
__device__ float g_pooled[Bz*Dz];
__device__ float g_w[Bz*Ez];
__device__ float g_part[(size_t)SPLITK*NROWS*NCOLS];   // 27.5 MB
__device__ __nv_bfloat16 g_Bh[(size_t)NCOLS*INz];
__device__ __nv_bfloat16 g_Bl[(size_t)NCOLS*INz];

// ---------------- PTX helpers (compute_80-safe) ----------------
__device__ __forceinline__ uint32_t smem_u32(const void* p) {
    uint32_t a;
    asm("{ .reg .u64 t; cvta.to.shared.u64 t, %1; cvt.u32.u64 %0, t; }" : "=r"(a) : "l"(p));
    return a;
}
#define CP16(dst, src)  asm volatile("cp.async.cg.shared.global [%0], [%1], 16;" :: "r"(dst), "l"(src) : "memory")
#define CP_COMMIT()     asm volatile("cp.async.commit_group;" ::: "memory")
#define CP_WAIT0()      asm volatile("cp.async.wait_group 0;" ::: "memory")
#define LDSM4(r0,r1,r2,r3,addr) \
    asm volatile("ldmatrix.sync.aligned.m8n8.x4.shared.b16 {%0,%1,%2,%3}, [%4];" \
        : "=r"(r0),"=r"(r1),"=r"(r2),"=r"(r3) : "r"(addr))
#define MMA(d, a, b0, b1) \
    asm volatile("mma.sync.aligned.m16n8k16.row.col.f32.bf16.bf16.f32 " \
        "{%0,%1,%2,%3},{%4,%5,%6,%7},{%8,%9},{%0,%1,%2,%3};" \
        : "+f"((d)[0]),"+f"((d)[1]),"+f"((d)[2]),"+f"((d)[3]) \
        : "r"((a)[0]),"r"((a)[1]),"r"((a)[2]),"r"((a)[3]), "r"(b0),"r"(b1))

__device__ __forceinline__ void cvt_hilo(float4 f, uint2& h, uint2& l) {
    __nv_bfloat162 h01 = __floats2bfloat162_rn(f.x, f.y);
    __nv_bfloat162 h23 = __floats2bfloat162_rn(f.z, f.w);
    float rx = f.x - __bfloat162float(h01.x);
    float ry = f.y - __bfloat162float(h01.y);
    float rz = f.z - __bfloat162float(h23.x);
    float rw = f.w - __bfloat162float(h23.y);
    __nv_bfloat162 l01 = __floats2bfloat162_rn(rx, ry);
    __nv_bfloat162 l23 = __floats2bfloat162_rn(rz, rw);
    h.x = reinterpret_cast<uint32_t&>(h01);
    h.y = reinterpret_cast<uint32_t&>(h23);
    l.x = reinterpret_cast<uint32_t&>(l01);
    l.y = reinterpret_cast<uint32_t&>(l23);
}

// ---------------- 0) pre-convert B-matrix (W_base ++ lora_A) to bf16 hi/lo ----
__global__ void bprep_kernel(const float* __restrict__ Wb, const float* __restrict__ lA) {
    int idx = blockIdx.x * 256 + threadIdx.x;
    if (idx >= NCOLS * (INz / 4)) return;
    int row = idx / (INz / 4);
    int c   = idx % (INz / 4);
    const float* src = (row < OUTz ? Wb + (size_t)row * INz
                                   : lA + (size_t)(row - OUTz) * INz) + c * 4;
    float4 f = *(const float4*)src;
    uint2 h, l; cvt_hilo(f, h, l);
    ((uint2*)g_Bh)[idx] = h;
    ((uint2*)g_Bl)[idx] = l;
}

// ---------------- 1) pool ----------------
__global__ void pool_kernel(const float* __restrict__ x) {
    int warp = (blockIdx.x * blockDim.x + threadIdx.x) >> 5;
    int lane = threadIdx.x & 31;
    if (warp >= Bz * Dz) return;
    int b = warp / Dz, d = warp % Dz;
    const float* base = x + ((size_t)(b * Vz) * Dz + d) * Pz;
    float s = 0.f;
    #pragma unroll
    for (int v = 0; v < Vz; v++) {
        float2 val = ((const float2*)(base + (size_t)v * Dz * Pz))[lane];
        s += val.x + val.y;
    }
    #pragma unroll
    for (int o = 16; o; o >>= 1) s += __shfl_xor_sync(0xffffffffu, s, o);
    if (lane == 0) g_pooled[warp] = s * (1.0f / (Vz * Pz));
}

// ---------------- 2) router ----------------
__global__ void router_kernel(const float* __restrict__ W1, const float* __restrict__ b1,
                              const float* __restrict__ W2, const float* __restrict__ b2,
                              float* __restrict__ out_probs) {
    __shared__ float sp[Dz];
    __shared__ float sh[Hz];
    __shared__ float sl[Ez];
    int b = blockIdx.x, t = threadIdx.x;
    for (int i = t; i < Dz; i += 256) sp[i] = g_pooled[b * Dz + i];
    __syncthreads();
    if (t < Hz) {
        float acc = b1[t];
        const float* w = W1 + (size_t)t * Dz;
        #pragma unroll 8
        for (int k = 0; k < Dz; k++) acc = fmaf(sp[k], w[k], acc);
        sh[t] = fmaxf(acc, 0.f);
    }
    __syncthreads();
    if (t < Ez) {
        float acc = b2[t];
        const float* w = W2 + (size_t)t * Hz;
        #pragma unroll 8
        for (int k = 0; k < Hz; k++) acc = fmaf(sh[k], w[k], acc);
        sl[t] = acc;
    }
    __syncthreads();
    if (t == 0) {
        float mx = -1e30f;
        #pragma unroll
        for (int e = 0; e < Ez; e++) mx = fmaxf(mx, sl[e]);
        float pr[Ez]; float se = 0.f;
        #pragma unroll
        for (int e = 0; e < Ez; e++) { pr[e] = expf(sl[e] - mx); se += pr[e]; }
        float inv = 1.0f / se;
        #pragma unroll
        for (int e = 0; e < Ez; e++) { pr[e] *= inv; out_probs[b * Ez + e] = pr[e]; }
        int i0 = 0;
        #pragma unroll
        for (int e = 1; e < Ez; e++) if (pr[e] > pr[i0]) i0 = e;
        int i1 = (i0 == 0) ? 1 : 0;
        #pragma unroll
        for (int e = 0; e < Ez; e++) if (e != i0 && pr[e] > pr[i1]) i1 = e;
        float s2 = pr[i0] + pr[i1];
        if (s2 < 1e-6f) s2 = 1e-6f;
        float inv2 = SCALE / s2;
        #pragma unroll
        for (int e = 0; e < Ez; e++) g_w[b * Ez + e] = 0.f;
        g_w[b * Ez + i0] = pr[i0] * inv2;
        g_w[b * Ez + i1] = pr[i1] * inv2;
    }
}

// ---------------- 3) mma.sync split-K GEMM (bf16 hi/lo, fp32 acc) ----------------
// grid (11, 64), 256 thr (8 warps: 4 along M x 2 along N), 2 CTA/SM
__global__ __launch_bounds__(256, 2)
void gemm_mma_kernel(const float* __restrict__ x) {
    extern __shared__ char smem[];
    const uint32_t sb = smem_u32(smem);
    const int t = threadIdx.x;
    const int lane = t & 31;
    const int wid = t >> 5;
    const int wm = wid & 3;
    const int wn = wid >> 2;
    const int m0 = blockIdx.x * MT;
    const int k0 = blockIdx.y * KC;

    // A loader: 2 float4 per thread per stage
    const float* aptr[2]; uint32_t asts[2]; bool aval[2];
    #pragma unroll
    for (int j = 0; j < 2; j++) {
        int idx = t + j * 256;
        int arow = idx >> 3, ac4 = idx & 7;
        aval[j] = (m0 + arow) < NROWS;
        aptr[j] = x + (size_t)(aval[j] ? m0 + arow : 0) * INz + k0 + ac4 * 4;
        asts[j] = (uint32_t)(arow * 80 + ac4 * 8);
    }
    // B loader: 5 x 16B cp.async per thread per stage
    const __nv_bfloat16* bsrc[5]; uint32_t bsts[5];
    #pragma unroll
    for (int j = 0; j < 5; j++) {
        int idx = t + j * 256;
        int plane = idx >= 640;
        int i2 = idx - plane * 640;
        int brow = i2 >> 2, bc = i2 & 3;
        bsrc[j] = (plane ? g_Bl : g_Bh) + (size_t)brow * INz + k0 + bc * 8;
        bsts[j] = (uint32_t)((plane ? BL_OFF : BH_OFF) + brow * 80 + bc * 16);
    }

    // ldmatrix lane addresses
    const uint32_t a_lane = (uint32_t)((wm * 16 + (lane & 15)) * 80 + (lane >> 4) * 16);
    const int q = (lane >> 3) & 3;
    const uint32_t b_lane = (uint32_t)(((q >> 1) * 8 + (lane & 7)) * 80 + (q & 1) * 16
                                       + wn * 80 * 80 + BH_OFF);

    float acc[10][4];
    #pragma unroll
    for (int j = 0; j < 10; j++)
        #pragma unroll
        for (int i = 0; i < 4; i++) acc[j][i] = 0.f;

    // prologue: stage 0
    float4 areg[2];
    #pragma unroll
    for (int j = 0; j < 2; j++)
        areg[j] = aval[j] ? *(const float4*)aptr[j] : make_float4(0.f, 0.f, 0.f, 0.f);
    #pragma unroll
    for (int j = 0; j < 5; j++) CP16(sb + bsts[j], bsrc[j]);
    CP_COMMIT();

    for (int s = 0; s < NSTEP; s++) {
        const uint32_t base = sb + (uint32_t)(s & 1) * STAGE;
        #pragma unroll
        for (int j = 0; j < 2; j++) {
            uint2 h, l; cvt_hilo(areg[j], h, l);
            *(uint2*)(smem + (base - sb) + AH_OFF + asts[j]) = h;
            *(uint2*)(smem + (base - sb) + AL_OFF + asts[j]) = l;
        }
        CP_WAIT0();
        __syncthreads();
        if (s + 1 < NSTEP) {
            const int koff = (s + 1) * KT;
            #pragma unroll
            for (int j = 0; j < 2; j++)
                areg[j] = aval[j] ? *(const float4*)(aptr[j] + koff)
                                  : make_float4(0.f, 0.f, 0.f, 0.f);
            const uint32_t nbase = sb + (uint32_t)((s + 1) & 1) * STAGE;
            #pragma unroll
            for (int j = 0; j < 5; j++) CP16(nbase + bsts[j], bsrc[j] + koff);
            CP_COMMIT();
        }
        // compute: register double-buffered B, distance-2 MMA ordering
        #pragma unroll
        for (int kk = 0; kk < 2; kk++) {
            uint32_t ah[4], al[4];
            LDSM4(ah[0], ah[1], ah[2], ah[3], base + AH_OFF + a_lane + kk * 32);
            LDSM4(al[0], al[1], al[2], al[3], base + AL_OFF + a_lane + kk * 32);
            uint32_t bh[2][4], bl[2][4];
            {
                const uint32_t ba = base + b_lane + kk * 32;
                LDSM4(bh[0][0], bh[0][1], bh[0][2], bh[0][3], ba);
                LDSM4(bl[0][0], bl[0][1], bl[0][2], bl[0][3], ba + (BL_OFF - BH_OFF));
            }
            #pragma unroll
            for (int jp = 0; jp < 5; jp++) {
                const int cur = jp & 1, nxt = cur ^ 1;
                if (jp < 4) {
                    const uint32_t ba = base + b_lane + (jp + 1) * 1280 + kk * 32;
                    LDSM4(bh[nxt][0], bh[nxt][1], bh[nxt][2], bh[nxt][3], ba);
                    LDSM4(bl[nxt][0], bl[nxt][1], bl[nxt][2], bl[nxt][3], ba + (BL_OFF - BH_OFF));
                }
                float* a0 = acc[jp * 2 + 0];
                float* a1 = acc[jp * 2 + 1];
                MMA(a0, ah, bh[cur][0], bh[cur][1]);
                MMA(a1, ah, bh[cur][2], bh[cur][3]);
                MMA(a0, ah, bl[cur][0], bl[cur][1]);
                MMA(a1, ah, bl[cur][2], bl[cur][3]);
                MMA(a0, al, bh[cur][0], bh[cur][1]);
                MMA(a1, al, bh[cur][2], bh[cur][3]);
            }
        }
        __syncthreads();
    }

    // epilogue: write split-K partials
    float* outp = g_part + (size_t)blockIdx.y * NROWS * NCOLS;
    const int r0 = m0 + wm * 16 + (lane >> 2);
    const int c0 = wn * 80 + (lane & 3) * 2;
    #pragma unroll
    for (int j = 0; j < 10; j++) {
        int col = c0 + j * 8;
        if (r0 < NROWS)
            *(float2*)(outp + (size_t)r0 * NCOLS + col) = make_float2(acc[j][0], acc[j][1]);
        if (r0 + 8 < NROWS)
            *(float2*)(outp + (size_t)(r0 + 8) * NCOLS + col) = make_float2(acc[j][2], acc[j][3]);
    }
}

// ---------------- 4) split-K reduce + bias + top-2 LoRA combine ----------------
__global__ void reduce_kernel(const float* __restrict__ b_base,
                              const float* __restrict__ lB,
                              float* __restrict__ out) {
    const int row = blockIdx.x;
    const int t = threadIdx.x;
    const int b = row / Vz;
    __shared__ float temp[Ez * Rz];
    float v = 0.f;
    #pragma unroll 16
    for (int s = 0; s < SPLITK; s++)
        v += g_part[((size_t)s * NROWS + row) * NCOLS + t];
    if (t >= OUTz) temp[t - OUTz] = v;
    __syncthreads();
    if (t < OUTz) {
        float o = b_base[t] + v;
        #pragma unroll
        for (int e = 0; e < Ez; e++) {
            float w = g_w[b * Ez + e];
            if (w != 0.f) {
                float d = 0.f;
                #pragma unroll
                for (int r = 0; r < Rz; r++)
                    d = fmaf(lB[((size_t)e * OUTz + t) * Rz + r], temp[e * Rz + r], d);
                o = fmaf(w, d, o);
            }
        }
        out[(size_t)row * OUTz + t] = o;
    }
}

// ---------------- launch ----------------
extern "C" void kernel_launch(void* const* d_in, const int* in_sizes, int n_in,
                              void* d_out, int out_size) {
    const float* x   = (const float*)d_in[0];
    const float* Wb  = (const float*)d_in[1];
    const float* bb  = (const float*)d_in[2];
    const float* W1  = (const float*)d_in[3];
    const float* b1v = (const float*)d_in[4];
    const float* W2  = (const float*)d_in[5];
    const float* b2v = (const float*)d_in[6];
    const float* lA  = (const float*)d_in[7];
    const float* lB  = (const float*)d_in[8];
    float* out = (float*)d_out;
    float* out_probs = out + (size_t)NROWS * OUTz;

    cudaFuncSetAttribute(gemm_mma_kernel, cudaFuncAttributeMaxDynamicSharedMemorySize, SM_TOTAL);

    bprep_kernel<<<(NCOLS * (INz / 4) + 255) / 256, 256>>>(Wb, lA);
    pool_kernel<<<(Bz * Dz) / 8, 256>>>(x);
    router_kernel<<<Bz, 256>>>(W1, b1v, W2, b2v, out_probs);
    gemm_mma_kernel<<<dim3(11, SPLITK), 256, SM_TOTAL>>>(x);
    reduce_kernel<<<NROWS, NCOLS>>>(bb, lB, out);
    (void)in_sizes; (void)n_in; (void)out_size;
}

// round 5
// speedup vs baseline: 2.0643x; 1.0411x over previous
#include <cuda_runtime.h>
#include <cuda_bf16.h>
#include <cstdint>

#define Bz 32
#define Vz 21
#define Dz 512
#define Pz 64
#define INz 32768
#define OUTz 96
#define Ez 8
#define Rz 8
#define Hz 256
#define NROWS (Bz*Vz)          /* 672 */
#define NCOLS (OUTz + Ez*Rz)   /* 160 */
#define SPLITK 64
#define KC (INz/SPLITK)        /* 512 */
#define SCALE 2.0f

// GEMM tiling
#define MT 64
#define KT 32
#define NSTEP (KC/KT)          /* 16 */
// smem layout (bytes): rows padded to 80B -> ldmatrix conflict-free
#define AH_OFF 0
#define AL_OFF 5120            /* 64*80 */
#define BH_OFF 10240
#define BL_OFF 23040           /* +160*80 */
#define STAGE  35840
#define SM_TOTAL (2*STAGE)     /* 71680 */

// ---------------- device scratch ----------------
__device__ float g_pooled[Bz*Dz];                  // raw sums (zeroed each launch)
__device__ float g_w[Bz*Ez];
__device__ float g_acc[NROWS*NCOLS];               // gemm accum (zeroed each launch)

// ---------------- PTX helpers ----------------
__device__ __forceinline__ uint32_t smem_u32(const void* p) {
    uint32_t a;
    asm("{ .reg .u64 t; cvta.to.shared.u64 t, %1; cvt.u32.u64 %0, t; }" : "=r"(a) : "l"(p));
    return a;
}
#define LDSM4(r0,r1,r2,r3,addr) \
    asm volatile("ldmatrix.sync.aligned.m8n8.x4.shared.b16 {%0,%1,%2,%3}, [%4];" \
        : "=r"(r0),"=r"(r1),"=r"(r2),"=r"(r3) : "r"(addr))
#define MMA(d, a, b0, b1) \
    asm volatile("mma.sync.aligned.m16n8k16.row.col.f32.bf16.bf16.f32 " \
        "{%0,%1,%2,%3},{%4,%5,%6,%7},{%8,%9},{%0,%1,%2,%3};" \
        : "+f"((d)[0]),"+f"((d)[1]),"+f"((d)[2]),"+f"((d)[3]) \
        : "r"((a)[0]),"r"((a)[1]),"r"((a)[2]),"r"((a)[3]), "r"(b0),"r"(b1))

__device__ __forceinline__ void cvt_hilo(float4 f, uint2& h, uint2& l) {
    __nv_bfloat162 h01 = __floats2bfloat162_rn(f.x, f.y);
    __nv_bfloat162 h23 = __floats2bfloat162_rn(f.z, f.w);
    float rx = f.x - __bfloat162float(h01.x);
    float ry = f.y - __bfloat162float(h01.y);
    float rz = f.z - __bfloat162float(h23.x);
    float rw = f.w - __bfloat162float(h23.y);
    __nv_bfloat162 l01 = __floats2bfloat162_rn(rx, ry);
    __nv_bfloat162 l23 = __floats2bfloat162_rn(rz, rw);
    h.x = reinterpret_cast<uint32_t&>(h01);
    h.y = reinterpret_cast<uint32_t&>(h23);
    l.x = reinterpret_cast<uint32_t&>(l01);
    l.y = reinterpret_cast<uint32_t&>(l23);
}

// ---------------- 0) zero scratch ----------------
__global__ void zero_kernel() {
    int i = blockIdx.x * 256 + threadIdx.x;
    if (i < Bz * Dz) g_pooled[i] = 0.f;
    if (i < NROWS * NCOLS) g_acc[i] = 0.f;
}

// ---------------- 1) fused gemm: MMA + pooled sums + atomic epilogue ----------
// grid (11, 64), 256 thr (8 warps: 4 along M x 2 along N), 2 CTA/SM
__global__ __launch_bounds__(256, 2)
void gemm_mma_kernel(const float* __restrict__ x,
                     const float* __restrict__ Wb,
                     const float* __restrict__ lA) {
    extern __shared__ char smem[];
    const uint32_t sb = smem_u32(smem);
    const int t = threadIdx.x;
    const int lane = t & 31;
    const int wid = t >> 5;
    const int wm = wid & 3;
    const int wn = wid >> 2;
    const int m0 = blockIdx.x * MT;
    const int k0 = blockIdx.y * KC;
    const int d0 = k0 >> 6;          // first d covered by this k-slice

    // A loader: 2 float4 per thread per stage
    const float* aptr[2]; uint32_t asts[2]; bool aval[2]; int abid[2];
    #pragma unroll
    for (int j = 0; j < 2; j++) {
        int idx = t + j * 256;
        int arow = idx >> 3, ac4 = idx & 7;
        int gr = m0 + arow;
        aval[j] = gr < NROWS;
        abid[j] = (aval[j] ? gr : 0) / Vz;
        aptr[j] = x + (size_t)(aval[j] ? gr : 0) * INz + k0 + ac4 * 4;
        asts[j] = (uint32_t)(arow * 80 + ac4 * 8);
    }
    // B loader: 5 float4 (fp32) per thread per stage, convert in-kernel
    const float* bsrcf[5]; uint32_t bsts[5];
    #pragma unroll
    for (int j = 0; j < 5; j++) {
        int idx = t + j * 256;
        int brow = idx >> 3, c4 = idx & 7;
        const float* rp = (brow < OUTz) ? (Wb + (size_t)brow * INz)
                                        : (lA + (size_t)(brow - OUTz) * INz);
        bsrcf[j] = rp + k0 + c4 * 4;
        bsts[j] = (uint32_t)(brow * 80 + c4 * 8);
    }

    // ldmatrix lane addresses
    const uint32_t a_lane = (uint32_t)((wm * 16 + (lane & 15)) * 80 + (lane >> 4) * 16);
    const int q = (lane >> 3) & 3;
    const uint32_t b_lane = (uint32_t)(((q >> 1) * 8 + (lane & 7)) * 80 + (q & 1) * 16
                                       + wn * 80 * 80 + BH_OFF);

    float acc[10][4];
    #pragma unroll
    for (int j = 0; j < 10; j++)
        #pragma unroll
        for (int i = 0; i < 4; i++) acc[j][i] = 0.f;

    // prologue: A regs for stage 0
    float4 areg[2];
    #pragma unroll
    for (int j = 0; j < 2; j++)
        areg[j] = aval[j] ? *(const float4*)aptr[j] : make_float4(0.f, 0.f, 0.f, 0.f);

    float rsum0 = 0.f, rsum1 = 0.f;

    for (int s = 0; s < NSTEP; s++) {
        const uint32_t base = sb + (uint32_t)(s & 1) * STAGE;
        char* smbase = smem + (size_t)(s & 1) * STAGE;
        const int koff = s * KT;
        // B: load fp32, convert, STS
        #pragma unroll
        for (int j = 0; j < 5; j++) {
            float4 f = *(const float4*)(bsrcf[j] + koff);
            uint2 h, l; cvt_hilo(f, h, l);
            *(uint2*)(smbase + BH_OFF + bsts[j]) = h;
            *(uint2*)(smbase + BL_OFF + bsts[j]) = l;
        }
        // A: convert prefetched regs, STS, accumulate pooled sums
        {
            uint2 h, l;
            cvt_hilo(areg[0], h, l);
            *(uint2*)(smbase + AH_OFF + asts[0]) = h;
            *(uint2*)(smbase + AL_OFF + asts[0]) = l;
            rsum0 += (areg[0].x + areg[0].y) + (areg[0].z + areg[0].w);
            cvt_hilo(areg[1], h, l);
            *(uint2*)(smbase + AH_OFF + asts[1]) = h;
            *(uint2*)(smbase + AL_OFF + asts[1]) = l;
            rsum1 += (areg[1].x + areg[1].y) + (areg[1].z + areg[1].w);
        }
        if (s & 1) {   // flush pooled sums for this d (2 stages = one d)
            int d = d0 + (s >> 1);
            if (aval[0]) atomicAdd(&g_pooled[abid[0] * Dz + d], rsum0);
            if (aval[1]) atomicAdd(&g_pooled[abid[1] * Dz + d], rsum1);
            rsum0 = 0.f; rsum1 = 0.f;
        }
        __syncthreads();
        // prefetch A(s+1) into regs — latency hidden under compute
        if (s + 1 < NSTEP) {
            const int knext = (s + 1) * KT;
            #pragma unroll
            for (int j = 0; j < 2; j++)
                areg[j] = aval[j] ? *(const float4*)(aptr[j] + knext)
                                  : make_float4(0.f, 0.f, 0.f, 0.f);
        }
        // compute: register double-buffered B, distance-2 MMA ordering
        #pragma unroll
        for (int kk = 0; kk < 2; kk++) {
            uint32_t ah[4], al[4];
            LDSM4(ah[0], ah[1], ah[2], ah[3], base + AH_OFF + a_lane + kk * 32);
            LDSM4(al[0], al[1], al[2], al[3], base + AL_OFF + a_lane + kk * 32);
            uint32_t bh[2][4], bl[2][4];
            {
                const uint32_t ba = base + b_lane + kk * 32;
                LDSM4(bh[0][0], bh[0][1], bh[0][2], bh[0][3], ba);
                LDSM4(bl[0][0], bl[0][1], bl[0][2], bl[0][3], ba + (BL_OFF - BH_OFF));
            }
            #pragma unroll
            for (int jp = 0; jp < 5; jp++) {
                const int cur = jp & 1, nxt = cur ^ 1;
                if (jp < 4) {
                    const uint32_t ba = base + b_lane + (jp + 1) * 1280 + kk * 32;
                    LDSM4(bh[nxt][0], bh[nxt][1], bh[nxt][2], bh[nxt][3], ba);
                    LDSM4(bl[nxt][0], bl[nxt][1], bl[nxt][2], bl[nxt][3], ba + (BL_OFF - BH_OFF));
                }
                float* a0 = acc[jp * 2 + 0];
                float* a1 = acc[jp * 2 + 1];
                MMA(a0, ah, bh[cur][0], bh[cur][1]);
                MMA(a1, ah, bh[cur][2], bh[cur][3]);
                MMA(a0, ah, bl[cur][0], bl[cur][1]);
                MMA(a1, ah, bl[cur][2], bl[cur][3]);
                MMA(a0, al, bh[cur][0], bh[cur][1]);
                MMA(a1, al, bh[cur][2], bh[cur][3]);
            }
        }
        // no trailing sync needed: next iter's STS hits the other buffer,
        // and the s+2 reuse is fenced by the s+1 barrier above.
    }

    // epilogue: atomic-reduce partials into g_acc
    const int r0 = m0 + wm * 16 + (lane >> 2);
    const int c0 = wn * 80 + (lane & 3) * 2;
    #pragma unroll
    for (int j = 0; j < 10; j++) {
        int col = c0 + j * 8;
        if (r0 < NROWS) {
            atomicAdd(&g_acc[r0 * NCOLS + col],     acc[j][0]);
            atomicAdd(&g_acc[r0 * NCOLS + col + 1], acc[j][1]);
        }
        if (r0 + 8 < NROWS) {
            atomicAdd(&g_acc[(r0 + 8) * NCOLS + col],     acc[j][2]);
            atomicAdd(&g_acc[(r0 + 8) * NCOLS + col + 1], acc[j][3]);
        }
    }
}

// ---------------- 2) router (after gemm; g_pooled holds raw sums) ----------
__global__ void router_kernel(const float* __restrict__ W1, const float* __restrict__ b1,
                              const float* __restrict__ W2, const float* __restrict__ b2,
                              float* __restrict__ out_probs) {
    __shared__ float sp[Dz];
    __shared__ float sh[Hz];
    __shared__ float sl[Ez];
    const float invVP = 1.0f / (Vz * Pz);
    int b = blockIdx.x, t = threadIdx.x;
    for (int i = t; i < Dz; i += 256) sp[i] = g_pooled[b * Dz + i] * invVP;
    __syncthreads();
    if (t < Hz) {
        float acc = b1[t];
        const float* w = W1 + (size_t)t * Dz;
        #pragma unroll 8
        for (int k = 0; k < Dz; k++) acc = fmaf(sp[k], w[k], acc);
        sh[t] = fmaxf(acc, 0.f);
    }
    __syncthreads();
    if (t < Ez) {
        float acc = b2[t];
        const float* w = W2 + (size_t)t * Hz;
        #pragma unroll 8
        for (int k = 0; k < Hz; k++) acc = fmaf(sh[k], w[k], acc);
        sl[t] = acc;
    }
    __syncthreads();
    if (t == 0) {
        float mx = -1e30f;
        #pragma unroll
        for (int e = 0; e < Ez; e++) mx = fmaxf(mx, sl[e]);
        float pr[Ez]; float se = 0.f;
        #pragma unroll
        for (int e = 0; e < Ez; e++) { pr[e] = expf(sl[e] - mx); se += pr[e]; }
        float inv = 1.0f / se;
        #pragma unroll
        for (int e = 0; e < Ez; e++) { pr[e] *= inv; out_probs[b * Ez + e] = pr[e]; }
        int i0 = 0;
        #pragma unroll
        for (int e = 1; e < Ez; e++) if (pr[e] > pr[i0]) i0 = e;
        int i1 = (i0 == 0) ? 1 : 0;
        #pragma unroll
        for (int e = 0; e < Ez; e++) if (e != i0 && pr[e] > pr[i1]) i1 = e;
        float s2 = pr[i0] + pr[i1];
        if (s2 < 1e-6f) s2 = 1e-6f;
        float inv2 = SCALE / s2;
        #pragma unroll
        for (int e = 0; e < Ez; e++) g_w[b * Ez + e] = 0.f;
        g_w[b * Ez + i0] = pr[i0] * inv2;
        g_w[b * Ez + i1] = pr[i1] * inv2;
    }
}

// ---------------- 3) final: bias + top-2 LoRA combine ----------------
__global__ void final_kernel(const float* __restrict__ b_base,
                             const float* __restrict__ lB,
                             float* __restrict__ out) {
    const int row = blockIdx.x;
    const int t = threadIdx.x;
    const int b = row / Vz;
    __shared__ float temp[Ez * Rz];
    float v = g_acc[row * NCOLS + t];
    if (t >= OUTz) temp[t - OUTz] = v;
    __syncthreads();
    if (t < OUTz) {
        float o = b_base[t] + v;
        #pragma unroll
        for (int e = 0; e < Ez; e++) {
            float w = g_w[b * Ez + e];
            if (w != 0.f) {
                float d = 0.f;
                #pragma unroll
                for (int r = 0; r < Rz; r++)
                    d = fmaf(lB[((size_t)e * OUTz + t) * Rz + r], temp[e * Rz + r], d);
                o = fmaf(w, d, o);
            }
        }
        out[(size_t)row * OUTz + t] = o;
    }
}

// ---------------- launch ----------------
extern "C" void kernel_launch(void* const* d_in, const int* in_sizes, int n_in,
                              void* d_out, int out_size) {
    const float* x   = (const float*)d_in[0];
    const float* Wb  = (const float*)d_in[1];
    const float* bb  = (const float*)d_in[2];
    const float* W1  = (const float*)d_in[3];
    const float* b1v = (const float*)d_in[4];
    const float* W2  = (const float*)d_in[5];
    const float* b2v = (const float*)d_in[6];
    const float* lA  = (const float*)d_in[7];
    const float* lB  = (const float*)d_in[8];
    float* out = (float*)d_out;
    float* out_probs = out + (size_t)NROWS * OUTz;

    cudaFuncSetAttribute(gemm_mma_kernel, cudaFuncAttributeMaxDynamicSharedMemorySize, SM_TOTAL);

    zero_kernel<<<(NROWS * NCOLS + 255) / 256, 256>>>();
    gemm_mma_kernel<<<dim3(11, SPLITK), 256, SM_TOTAL>>>(x, Wb, lA);
    router_kernel<<<Bz, 256>>>(W1, b1v, W2, b2v, out_probs);
    final_kernel<<<NROWS, NCOLS>>>(bb, lB, out);
    (void)in_sizes; (void)n_in; (void)out_size;
}

// round 6
// speedup vs baseline: 2.1161x; 1.0251x over previous
#include <cuda_runtime.h>
#include <cuda_bf16.h>
#include <cstdint>

#define Bz 32
#define Vz 21
#define Dz 512
#define Pz 64
#define INz 32768
#define OUTz 96
#define Ez 8
#define Rz 8
#define Hz 256
#define NROWS (Bz*Vz)          /* 672 */
#define NCOLS (OUTz + Ez*Rz)   /* 160 */
#define SPLITK 64
#define KC (INz/SPLITK)        /* 512 */
#define SCALE 2.0f

// GEMM tiling
#define MT 64
#define KT 32
#define NSTEP (KC/KT)          /* 16 */
#define AH_OFF 0
#define AL_OFF 5120
#define BH_OFF 10240
#define BL_OFF 23040
#define STAGE  35840
#define SM_TOTAL (2*STAGE)     /* 71680 */

// ---------------- device scratch ----------------
__device__ float g_pooled[Bz*Dz];                  // raw sums (zeroed per launch)
__device__ float g_w[Bz*Ez];
__device__ float g_acc[NROWS*NCOLS];               // gemm accum (zeroed per launch)
__device__ __nv_bfloat16 g_Bh[(size_t)NCOLS*INz];
__device__ __nv_bfloat16 g_Bl[(size_t)NCOLS*INz];

// ---------------- PTX helpers ----------------
__device__ __forceinline__ uint32_t smem_u32(const void* p) {
    uint32_t a;
    asm("{ .reg .u64 t; cvta.to.shared.u64 t, %1; cvt.u32.u64 %0, t; }" : "=r"(a) : "l"(p));
    return a;
}
#define CP16(dst, src)  asm volatile("cp.async.cg.shared.global [%0], [%1], 16;" :: "r"(dst), "l"(src) : "memory")
#define CP_COMMIT()     asm volatile("cp.async.commit_group;" ::: "memory")
#define CP_WAIT0()      asm volatile("cp.async.wait_group 0;" ::: "memory")
#define LDSM4(r0,r1,r2,r3,addr) \
    asm volatile("ldmatrix.sync.aligned.m8n8.x4.shared.b16 {%0,%1,%2,%3}, [%4];" \
        : "=r"(r0),"=r"(r1),"=r"(r2),"=r"(r3) : "r"(addr))
#define MMA(d, a, b0, b1) \
    asm volatile("mma.sync.aligned.m16n8k16.row.col.f32.bf16.bf16.f32 " \
        "{%0,%1,%2,%3},{%4,%5,%6,%7},{%8,%9},{%0,%1,%2,%3};" \
        : "+f"((d)[0]),"+f"((d)[1]),"+f"((d)[2]),"+f"((d)[3]) \
        : "r"((a)[0]),"r"((a)[1]),"r"((a)[2]),"r"((a)[3]), "r"(b0),"r"(b1))

__device__ __forceinline__ void cvt_hilo(float4 f, uint2& h, uint2& l) {
    __nv_bfloat162 h01 = __floats2bfloat162_rn(f.x, f.y);
    __nv_bfloat162 h23 = __floats2bfloat162_rn(f.z, f.w);
    float rx = f.x - __bfloat162float(h01.x);
    float ry = f.y - __bfloat162float(h01.y);
    float rz = f.z - __bfloat162float(h23.x);
    float rw = f.w - __bfloat162float(h23.y);
    __nv_bfloat162 l01 = __floats2bfloat162_rn(rx, ry);
    __nv_bfloat162 l23 = __floats2bfloat162_rn(rz, rw);
    h.x = reinterpret_cast<uint32_t&>(h01);
    h.y = reinterpret_cast<uint32_t&>(h23);
    l.x = reinterpret_cast<uint32_t&>(l01);
    l.y = reinterpret_cast<uint32_t&>(l23);
}

// ---------------- 0) zero scratch ----------------
__global__ void zero_kernel() {
    int i = blockIdx.x * 256 + threadIdx.x;
    if (i < Bz * Dz) g_pooled[i] = 0.f;
    if (i < NROWS * NCOLS) g_acc[i] = 0.f;
}

// ---------------- 0b) pre-convert B-matrix to bf16 hi/lo ----------------
__global__ void bprep_kernel(const float* __restrict__ Wb, const float* __restrict__ lA) {
    int idx = blockIdx.x * 256 + threadIdx.x;
    if (idx >= NCOLS * (INz / 4)) return;
    int row = idx / (INz / 4);
    int c   = idx % (INz / 4);
    const float* src = (row < OUTz ? Wb + (size_t)row * INz
                                   : lA + (size_t)(row - OUTz) * INz) + c * 4;
    float4 f = *(const float4*)src;
    uint2 h, l; cvt_hilo(f, h, l);
    ((uint2*)g_Bh)[idx] = h;
    ((uint2*)g_Bl)[idx] = l;
}

// ---------------- 1) fused gemm: MMA + pooled sums + atomic epilogue -------
// grid (11, 64), 256 thr (8 warps: 4 M x 2 N), 2 CTA/SM
__global__ __launch_bounds__(256, 2)
void gemm_mma_kernel(const float* __restrict__ x) {
    extern __shared__ char smem[];
    const uint32_t sb = smem_u32(smem);
    const int t = threadIdx.x;
    const int lane = t & 31;
    const int wid = t >> 5;
    const int wm = wid & 3;
    const int wn = wid >> 2;
    const int m0 = blockIdx.x * MT;
    const int k0 = blockIdx.y * KC;
    const int d0 = k0 >> 6;

    // A loader: 2 float4 per thread per stage
    const float* aptr[2]; uint32_t asts[2]; bool aval[2]; int abid[2];
    #pragma unroll
    for (int j = 0; j < 2; j++) {
        int idx = t + j * 256;
        int arow = idx >> 3, ac4 = idx & 7;
        int gr = m0 + arow;
        aval[j] = gr < NROWS;
        abid[j] = (aval[j] ? gr : 0) / Vz;
        aptr[j] = x + (size_t)(aval[j] ? gr : 0) * INz + k0 + ac4 * 4;
        asts[j] = (uint32_t)(arow * 80 + ac4 * 8);
    }
    // B loader: 5 x 16B cp.async per thread per stage (bf16 planes)
    const __nv_bfloat16* bsrc[5]; uint32_t bsts[5];
    #pragma unroll
    for (int j = 0; j < 5; j++) {
        int idx = t + j * 256;
        int plane = idx >= 640;
        int i2 = idx - plane * 640;
        int brow = i2 >> 2, bc = i2 & 3;
        bsrc[j] = (plane ? g_Bl : g_Bh) + (size_t)brow * INz + k0 + bc * 8;
        bsts[j] = (uint32_t)((plane ? BL_OFF : BH_OFF) + brow * 80 + bc * 16);
    }

    // ldmatrix lane addresses
    const uint32_t a_lane = (uint32_t)((wm * 16 + (lane & 15)) * 80 + (lane >> 4) * 16);
    const int q = (lane >> 3) & 3;
    const uint32_t b_lane = (uint32_t)(((q >> 1) * 8 + (lane & 7)) * 80 + (q & 1) * 16
                                       + wn * 80 * 80 + BH_OFF);

    float acc[10][4];
    #pragma unroll
    for (int j = 0; j < 10; j++)
        #pragma unroll
        for (int i = 0; i < 4; i++) acc[j][i] = 0.f;

    // prologue: stage 0
    float4 areg[2];
    #pragma unroll
    for (int j = 0; j < 2; j++)
        areg[j] = aval[j] ? *(const float4*)aptr[j] : make_float4(0.f, 0.f, 0.f, 0.f);
    #pragma unroll
    for (int j = 0; j < 5; j++) CP16(sb + bsts[j], bsrc[j]);
    CP_COMMIT();

    float rsum0 = 0.f, rsum1 = 0.f;

    for (int s = 0; s < NSTEP; s++) {
        const uint32_t base = sb + (uint32_t)(s & 1) * STAGE;
        // convert + store A hi/lo; accumulate pooled sums
        #pragma unroll
        for (int j = 0; j < 2; j++) {
            uint2 h, l; cvt_hilo(areg[j], h, l);
            *(uint2*)(smem + (base - sb) + AH_OFF + asts[j]) = h;
            *(uint2*)(smem + (base - sb) + AL_OFF + asts[j]) = l;
        }
        rsum0 += (areg[0].x + areg[0].y) + (areg[0].z + areg[0].w);
        rsum1 += (areg[1].x + areg[1].y) + (areg[1].z + areg[1].w);
        if (s & 1) {   // one d per 2 stages: oct-reduce then single atomic per 8 lanes
            float v0 = rsum0, v1 = rsum1;
            #pragma unroll
            for (int o = 4; o; o >>= 1) {
                v0 += __shfl_down_sync(0xffffffffu, v0, o, 8);
                v1 += __shfl_down_sync(0xffffffffu, v1, o, 8);
            }
            if ((t & 7) == 0) {
                int d = d0 + (s >> 1);
                if (aval[0]) atomicAdd(&g_pooled[abid[0] * Dz + d], v0);
                if (aval[1]) atomicAdd(&g_pooled[abid[1] * Dz + d], v1);
            }
            rsum0 = 0.f; rsum1 = 0.f;
        }
        CP_WAIT0();
        __syncthreads();
        if (s + 1 < NSTEP) {
            const int koff = (s + 1) * KT;
            #pragma unroll
            for (int j = 0; j < 2; j++)
                areg[j] = aval[j] ? *(const float4*)(aptr[j] + koff)
                                  : make_float4(0.f, 0.f, 0.f, 0.f);
            const uint32_t nbase = sb + (uint32_t)((s + 1) & 1) * STAGE;
            #pragma unroll
            for (int j = 0; j < 5; j++) CP16(nbase + bsts[j], bsrc[j] + koff);
            CP_COMMIT();
        }
        // compute: register double-buffered B, distance-2 MMA ordering
        #pragma unroll
        for (int kk = 0; kk < 2; kk++) {
            uint32_t ah[4], al[4];
            LDSM4(ah[0], ah[1], ah[2], ah[3], base + AH_OFF + a_lane + kk * 32);
            LDSM4(al[0], al[1], al[2], al[3], base + AL_OFF + a_lane + kk * 32);
            uint32_t bh[2][4], bl[2][4];
            {
                const uint32_t ba = base + b_lane + kk * 32;
                LDSM4(bh[0][0], bh[0][1], bh[0][2], bh[0][3], ba);
                LDSM4(bl[0][0], bl[0][1], bl[0][2], bl[0][3], ba + (BL_OFF - BH_OFF));
            }
            #pragma unroll
            for (int jp = 0; jp < 5; jp++) {
                const int cur = jp & 1, nxt = cur ^ 1;
                if (jp < 4) {
                    const uint32_t ba = base + b_lane + (jp + 1) * 1280 + kk * 32;
                    LDSM4(bh[nxt][0], bh[nxt][1], bh[nxt][2], bh[nxt][3], ba);
                    LDSM4(bl[nxt][0], bl[nxt][1], bl[nxt][2], bl[nxt][3], ba + (BL_OFF - BH_OFF));
                }
                float* a0 = acc[jp * 2 + 0];
                float* a1 = acc[jp * 2 + 1];
                MMA(a0, ah, bh[cur][0], bh[cur][1]);
                MMA(a1, ah, bh[cur][2], bh[cur][3]);
                MMA(a0, ah, bl[cur][0], bl[cur][1]);
                MMA(a1, ah, bl[cur][2], bl[cur][3]);
                MMA(a0, al, bh[cur][0], bh[cur][1]);
                MMA(a1, al, bh[cur][2], bh[cur][3]);
            }
        }
        __syncthreads();
    }

    // epilogue: atomic-reduce into g_acc
    const int r0 = m0 + wm * 16 + (lane >> 2);
    const int c0 = wn * 80 + (lane & 3) * 2;
    #pragma unroll
    for (int j = 0; j < 10; j++) {
        int col = c0 + j * 8;
        if (r0 < NROWS) {
            atomicAdd(&g_acc[r0 * NCOLS + col],     acc[j][0]);
            atomicAdd(&g_acc[r0 * NCOLS + col + 1], acc[j][1]);
        }
        if (r0 + 8 < NROWS) {
            atomicAdd(&g_acc[(r0 + 8) * NCOLS + col],     acc[j][2]);
            atomicAdd(&g_acc[(r0 + 8) * NCOLS + col + 1], acc[j][3]);
        }
    }
}

// ---------------- 2) router (g_pooled holds raw sums) ----------------
__global__ void router_kernel(const float* __restrict__ W1, const float* __restrict__ b1,
                              const float* __restrict__ W2, const float* __restrict__ b2,
                              float* __restrict__ out_probs) {
    __shared__ float sp[Dz];
    __shared__ float sh[Hz];
    __shared__ float sl[Ez];
    const float invVP = 1.0f / (Vz * Pz);
    int b = blockIdx.x, t = threadIdx.x;
    for (int i = t; i < Dz; i += 256) sp[i] = g_pooled[b * Dz + i] * invVP;
    __syncthreads();
    if (t < Hz) {
        float acc = b1[t];
        const float* w = W1 + (size_t)t * Dz;
        #pragma unroll 8
        for (int k = 0; k < Dz; k++) acc = fmaf(sp[k], w[k], acc);
        sh[t] = fmaxf(acc, 0.f);
    }
    __syncthreads();
    if (t < Ez) {
        float acc = b2[t];
        const float* w = W2 + (size_t)t * Hz;
        #pragma unroll 8
        for (int k = 0; k < Hz; k++) acc = fmaf(sh[k], w[k], acc);
        sl[t] = acc;
    }
    __syncthreads();
    if (t == 0) {
        float mx = -1e30f;
        #pragma unroll
        for (int e = 0; e < Ez; e++) mx = fmaxf(mx, sl[e]);
        float pr[Ez]; float se = 0.f;
        #pragma unroll
        for (int e = 0; e < Ez; e++) { pr[e] = expf(sl[e] - mx); se += pr[e]; }
        float inv = 1.0f / se;
        #pragma unroll
        for (int e = 0; e < Ez; e++) { pr[e] *= inv; out_probs[b * Ez + e] = pr[e]; }
        int i0 = 0;
        #pragma unroll
        for (int e = 1; e < Ez; e++) if (pr[e] > pr[i0]) i0 = e;
        int i1 = (i0 == 0) ? 1 : 0;
        #pragma unroll
        for (int e = 0; e < Ez; e++) if (e != i0 && pr[e] > pr[i1]) i1 = e;
        float s2 = pr[i0] + pr[i1];
        if (s2 < 1e-6f) s2 = 1e-6f;
        float inv2 = SCALE / s2;
        #pragma unroll
        for (int e = 0; e < Ez; e++) g_w[b * Ez + e] = 0.f;
        g_w[b * Ez + i0] = pr[i0] * inv2;
        g_w[b * Ez + i1] = pr[i1] * inv2;
    }
}

// ---------------- 3) final: bias + top-2 LoRA combine ----------------
__global__ void final_kernel(const float* __restrict__ b_base,
                             const float* __restrict__ lB,
                             float* __restrict__ out) {
    const int row = blockIdx.x;
    const int t = threadIdx.x;
    const int b = row / Vz;
    __shared__ float temp[Ez * Rz];
    float v = g_acc[row * NCOLS + t];
    if (t >= OUTz) temp[t - OUTz] = v;
    __syncthreads();
    if (t < OUTz) {
        float o = b_base[t] + v;
        #pragma unroll
        for (int e = 0; e < Ez; e++) {
            float w = g_w[b * Ez + e];
            if (w != 0.f) {
                float d = 0.f;
                #pragma unroll
                for (int r = 0; r < Rz; r++)
                    d = fmaf(lB[((size_t)e * OUTz + t) * Rz + r], temp[e * Rz + r], d);
                o = fmaf(w, d, o);
            }
        }
        out[(size_t)row * OUTz + t] = o;
    }
}

// ---------------- launch ----------------
extern "C" void kernel_launch(void* const* d_in, const int* in_sizes, int n_in,
                              void* d_out, int out_size) {
    const float* x   = (const float*)d_in[0];
    const float* Wb  = (const float*)d_in[1];
    const float* bb  = (const float*)d_in[2];
    const float* W1  = (const float*)d_in[3];
    const float* b1v = (const float*)d_in[4];
    const float* W2  = (const float*)d_in[5];
    const float* b2v = (const float*)d_in[6];
    const float* lA  = (const float*)d_in[7];
    const float* lB  = (const float*)d_in[8];
    float* out = (float*)d_out;
    float* out_probs = out + (size_t)NROWS * OUTz;

    cudaFuncSetAttribute(gemm_mma_kernel, cudaFuncAttributeMaxDynamicSharedMemorySize, SM_TOTAL);

    zero_kernel<<<(NROWS * NCOLS + 255) / 256, 256>>>();
    bprep_kernel<<<(NCOLS * (INz / 4) + 255) / 256, 256>>>(Wb, lA);
    gemm_mma_kernel<<<dim3(11, SPLITK), 256, SM_TOTAL>>>(x);
    router_kernel<<<Bz, 256>>>(W1, b1v, W2, b2v, out_probs);
    final_kernel<<<NROWS, NCOLS>>>(bb, lB, out);
    (void)in_sizes; (void)n_in; (void)out_size;
}

// round 7
// speedup vs baseline: 2.6040x; 1.2306x over previous
#include <cuda_runtime.h>
#include <cuda_bf16.h>
#include <cstdint>

#define Bz 32
#define Vz 21
#define Dz 512
#define Pz 64
#define INz 32768
#define OUTz 96
#define Ez 8
#define Rz 8
#define Hz 256
#define NROWS (Bz*Vz)          /* 672 */
#define NCOLS (OUTz + Ez*Rz)   /* 160 */
#define SPLITK 64
#define KC (INz/SPLITK)        /* 512 */
#define SCALE 2.0f

// GEMM tiling
#define MT 64
#define KT 32
#define NSTEP (KC/KT)          /* 16 */
#define AH_OFF 0
#define AL_OFF 5120
#define BH_OFF 10240
#define BL_OFF 23040
#define STAGE  35840
#define SM_TOTAL (2*STAGE)     /* 71680 */

// ---------------- device scratch ----------------
__device__ float g_pooled[Bz*Dz];                  // raw sums (zeroed per launch)
__device__ float g_w[Bz*Ez];
__device__ float g_acc[NROWS*NCOLS];               // gemm accum (zeroed per launch)
__device__ __nv_bfloat16 g_Bh[(size_t)NCOLS*INz];
__device__ __nv_bfloat16 g_Bl[(size_t)NCOLS*INz];

// ---------------- PTX helpers ----------------
__device__ __forceinline__ uint32_t smem_u32(const void* p) {
    uint32_t a;
    asm("{ .reg .u64 t; cvta.to.shared.u64 t, %1; cvt.u32.u64 %0, t; }" : "=r"(a) : "l"(p));
    return a;
}
#define CP16(dst, src)  asm volatile("cp.async.cg.shared.global [%0], [%1], 16;" :: "r"(dst), "l"(src) : "memory")
#define CP_COMMIT()     asm volatile("cp.async.commit_group;" ::: "memory")
#define CP_WAIT0()      asm volatile("cp.async.wait_group 0;" ::: "memory")
#define LDSM4(r0,r1,r2,r3,addr) \
    asm volatile("ldmatrix.sync.aligned.m8n8.x4.shared.b16 {%0,%1,%2,%3}, [%4];" \
        : "=r"(r0),"=r"(r1),"=r"(r2),"=r"(r3) : "r"(addr))
#define MMA(d, a, b0, b1) \
    asm volatile("mma.sync.aligned.m16n8k16.row.col.f32.bf16.bf16.f32 " \
        "{%0,%1,%2,%3},{%4,%5,%6,%7},{%8,%9},{%0,%1,%2,%3};" \
        : "+f"((d)[0]),"+f"((d)[1]),"+f"((d)[2]),"+f"((d)[3]) \
        : "r"((a)[0]),"r"((a)[1]),"r"((a)[2]),"r"((a)[3]), "r"(b0),"r"(b1))

__device__ __forceinline__ void cvt_hilo(float4 f, uint2& h, uint2& l) {
    __nv_bfloat162 h01 = __floats2bfloat162_rn(f.x, f.y);
    __nv_bfloat162 h23 = __floats2bfloat162_rn(f.z, f.w);
    float rx = f.x - __bfloat162float(h01.x);
    float ry = f.y - __bfloat162float(h01.y);
    float rz = f.z - __bfloat162float(h23.x);
    float rw = f.w - __bfloat162float(h23.y);
    __nv_bfloat162 l01 = __floats2bfloat162_rn(rx, ry);
    __nv_bfloat162 l23 = __floats2bfloat162_rn(rz, rw);
    h.x = reinterpret_cast<uint32_t&>(h01);
    h.y = reinterpret_cast<uint32_t&>(h23);
    l.x = reinterpret_cast<uint32_t&>(l01);
    l.y = reinterpret_cast<uint32_t&>(l23);
}

// ---------------- 0) bprep + zero (fused) ----------------
__global__ void bprep_kernel(const float* __restrict__ Wb, const float* __restrict__ lA) {
    int idx = blockIdx.x * 256 + threadIdx.x;
    // zeroing piggy-back (first blocks)
    if (idx < Bz * Dz) g_pooled[idx] = 0.f;
    if (idx < NROWS * NCOLS) g_acc[idx] = 0.f;
    if (idx >= NCOLS * (INz / 4)) return;
    int row = idx / (INz / 4);
    int c   = idx % (INz / 4);
    const float* src = (row < OUTz ? Wb + (size_t)row * INz
                                   : lA + (size_t)(row - OUTz) * INz) + c * 4;
    float4 f = *(const float4*)src;
    uint2 h, l; cvt_hilo(f, h, l);
    ((uint2*)g_Bh)[idx] = h;
    ((uint2*)g_Bl)[idx] = l;
}

// ---------------- 1) fused gemm: MMA + pooled sums + atomic epilogue -------
// grid (11, 64), 256 thr (8 warps: 4 M x 2 N), 2 CTA/SM
__global__ __launch_bounds__(256, 2)
void gemm_mma_kernel(const float* __restrict__ x) {
    extern __shared__ char smem[];
    const uint32_t sb = smem_u32(smem);
    const int t = threadIdx.x;
    const int lane = t & 31;
    const int wid = t >> 5;
    const int wm = wid & 3;
    const int wn = wid >> 2;
    const int m0 = blockIdx.x * MT;
    const int k0 = blockIdx.y * KC;
    const int d0 = k0 >> 6;

    // A loader: 2 float4 per thread per stage
    const float* aptr[2]; uint32_t asts[2]; bool aval[2]; int abid[2];
    #pragma unroll
    for (int j = 0; j < 2; j++) {
        int idx = t + j * 256;
        int arow = idx >> 3, ac4 = idx & 7;
        int gr = m0 + arow;
        aval[j] = gr < NROWS;
        abid[j] = (aval[j] ? gr : 0) / Vz;
        aptr[j] = x + (size_t)(aval[j] ? gr : 0) * INz + k0 + ac4 * 4;
        asts[j] = (uint32_t)(arow * 80 + ac4 * 8);
    }
    // B loader: 5 x 16B cp.async per thread per stage (bf16 planes)
    const __nv_bfloat16* bsrc[5]; uint32_t bsts[5];
    #pragma unroll
    for (int j = 0; j < 5; j++) {
        int idx = t + j * 256;
        int plane = idx >= 640;
        int i2 = idx - plane * 640;
        int brow = i2 >> 2, bc = i2 & 3;
        bsrc[j] = (plane ? g_Bl : g_Bh) + (size_t)brow * INz + k0 + bc * 8;
        bsts[j] = (uint32_t)((plane ? BL_OFF : BH_OFF) + brow * 80 + bc * 16);
    }

    // ldmatrix lane addresses
    const uint32_t a_lane = (uint32_t)((wm * 16 + (lane & 15)) * 80 + (lane >> 4) * 16);
    const int q = (lane >> 3) & 3;
    const uint32_t b_lane = (uint32_t)(((q >> 1) * 8 + (lane & 7)) * 80 + (q & 1) * 16
                                       + wn * 80 * 80 + BH_OFF);

    float acc[10][4];
    #pragma unroll
    for (int j = 0; j < 10; j++)
        #pragma unroll
        for (int i = 0; i < 4; i++) acc[j][i] = 0.f;

    // prologue: stage 0
    float4 areg[2];
    #pragma unroll
    for (int j = 0; j < 2; j++)
        areg[j] = aval[j] ? *(const float4*)aptr[j] : make_float4(0.f, 0.f, 0.f, 0.f);
    #pragma unroll
    for (int j = 0; j < 5; j++) CP16(sb + bsts[j], bsrc[j]);
    CP_COMMIT();

    float rsum0 = 0.f, rsum1 = 0.f;

    for (int s = 0; s < NSTEP; s++) {
        const uint32_t base = sb + (uint32_t)(s & 1) * STAGE;
        // convert + store A hi/lo; accumulate pooled sums
        #pragma unroll
        for (int j = 0; j < 2; j++) {
            uint2 h, l; cvt_hilo(areg[j], h, l);
            *(uint2*)(smem + (base - sb) + AH_OFF + asts[j]) = h;
            *(uint2*)(smem + (base - sb) + AL_OFF + asts[j]) = l;
        }
        rsum0 += (areg[0].x + areg[0].y) + (areg[0].z + areg[0].w);
        rsum1 += (areg[1].x + areg[1].y) + (areg[1].z + areg[1].w);
        if (s & 1) {   // one d per 2 stages: oct-reduce then 1 atomic / 8 lanes
            float v0 = rsum0, v1 = rsum1;
            #pragma unroll
            for (int o = 4; o; o >>= 1) {
                v0 += __shfl_down_sync(0xffffffffu, v0, o, 8);
                v1 += __shfl_down_sync(0xffffffffu, v1, o, 8);
            }
            if ((t & 7) == 0) {
                int d = d0 + (s >> 1);
                if (aval[0]) atomicAdd(&g_pooled[abid[0] * Dz + d], v0);
                if (aval[1]) atomicAdd(&g_pooled[abid[1] * Dz + d], v1);
            }
            rsum0 = 0.f; rsum1 = 0.f;
        }
        CP_WAIT0();
        __syncthreads();
        if (s + 1 < NSTEP) {
            const int koff = (s + 1) * KT;
            #pragma unroll
            for (int j = 0; j < 2; j++)
                areg[j] = aval[j] ? *(const float4*)(aptr[j] + koff)
                                  : make_float4(0.f, 0.f, 0.f, 0.f);
            const uint32_t nbase = sb + (uint32_t)((s + 1) & 1) * STAGE;
            #pragma unroll
            for (int j = 0; j < 5; j++) CP16(nbase + bsts[j], bsrc[j] + koff);
            CP_COMMIT();
        }
        // compute: register double-buffered B, distance-2 MMA ordering
        #pragma unroll
        for (int kk = 0; kk < 2; kk++) {
            uint32_t ah[4], al[4];
            LDSM4(ah[0], ah[1], ah[2], ah[3], base + AH_OFF + a_lane + kk * 32);
            LDSM4(al[0], al[1], al[2], al[3], base + AL_OFF + a_lane + kk * 32);
            uint32_t bh[2][4], bl[2][4];
            {
                const uint32_t ba = base + b_lane + kk * 32;
                LDSM4(bh[0][0], bh[0][1], bh[0][2], bh[0][3], ba);
                LDSM4(bl[0][0], bl[0][1], bl[0][2], bl[0][3], ba + (BL_OFF - BH_OFF));
            }
            #pragma unroll
            for (int jp = 0; jp < 5; jp++) {
                const int cur = jp & 1, nxt = cur ^ 1;
                if (jp < 4) {
                    const uint32_t ba = base + b_lane + (jp + 1) * 1280 + kk * 32;
                    LDSM4(bh[nxt][0], bh[nxt][1], bh[nxt][2], bh[nxt][3], ba);
                    LDSM4(bl[nxt][0], bl[nxt][1], bl[nxt][2], bl[nxt][3], ba + (BL_OFF - BH_OFF));
                }
                float* a0 = acc[jp * 2 + 0];
                float* a1 = acc[jp * 2 + 1];
                MMA(a0, ah, bh[cur][0], bh[cur][1]);
                MMA(a1, ah, bh[cur][2], bh[cur][3]);
                MMA(a0, ah, bl[cur][0], bl[cur][1]);
                MMA(a1, ah, bl[cur][2], bl[cur][3]);
                MMA(a0, al, bh[cur][0], bh[cur][1]);
                MMA(a1, al, bh[cur][2], bh[cur][3]);
            }
        }
        __syncthreads();
    }

    // epilogue: atomic-reduce into g_acc
    const int r0 = m0 + wm * 16 + (lane >> 2);
    const int c0 = wn * 80 + (lane & 3) * 2;
    #pragma unroll
    for (int j = 0; j < 10; j++) {
        int col = c0 + j * 8;
        if (r0 < NROWS) {
            atomicAdd(&g_acc[r0 * NCOLS + col],     acc[j][0]);
            atomicAdd(&g_acc[r0 * NCOLS + col + 1], acc[j][1]);
        }
        if (r0 + 8 < NROWS) {
            atomicAdd(&g_acc[(r0 + 8) * NCOLS + col],     acc[j][2]);
            atomicAdd(&g_acc[(r0 + 8) * NCOLS + col + 1], acc[j][3]);
        }
    }
}

// ---------------- 2) router — warp-per-row, coalesced ----------------
__global__ void router_kernel(const float* __restrict__ W1, const float* __restrict__ b1,
                              const float* __restrict__ W2, const float* __restrict__ b2,
                              float* __restrict__ out_probs) {
    __shared__ float sp[Dz];
    __shared__ float sh[Hz];
    __shared__ float sl[Ez];
    const float invVP = 1.0f / (Vz * Pz);
    const int b = blockIdx.x, t = threadIdx.x;
    const int warp = t >> 5, lane = t & 31;
    for (int i = t; i < Dz; i += 256) sp[i] = g_pooled[b * Dz + i] * invVP;
    __syncthreads();
    // h = relu(W1 @ sp + b1): warp per row, lanes stride K (coalesced)
    #pragma unroll
    for (int rr = 0; rr < Hz / 8; rr++) {         // 32 rows per warp
        int r = warp * (Hz / 8) + rr;
        const float* w = W1 + (size_t)r * Dz;
        float acc = 0.f;
        #pragma unroll
        for (int k = 0; k < Dz / 32; k++) acc = fmaf(sp[k * 32 + lane], w[k * 32 + lane], acc);
        #pragma unroll
        for (int o = 16; o; o >>= 1) acc += __shfl_xor_sync(0xffffffffu, acc, o);
        if (lane == 0) sh[r] = fmaxf(acc + b1[r], 0.f);
    }
    __syncthreads();
    // logits: warp e computes logit e (warps 0..7)
    if (warp < Ez) {
        const float* w = W2 + (size_t)warp * Hz;
        float acc = 0.f;
        #pragma unroll
        for (int k = 0; k < Hz / 32; k++) acc = fmaf(sh[k * 32 + lane], w[k * 32 + lane], acc);
        #pragma unroll
        for (int o = 16; o; o >>= 1) acc += __shfl_xor_sync(0xffffffffu, acc, o);
        if (lane == 0) sl[warp] = acc + b2[warp];
    }
    __syncthreads();
    if (t == 0) {
        float mx = -1e30f;
        #pragma unroll
        for (int e = 0; e < Ez; e++) mx = fmaxf(mx, sl[e]);
        float pr[Ez]; float se = 0.f;
        #pragma unroll
        for (int e = 0; e < Ez; e++) { pr[e] = expf(sl[e] - mx); se += pr[e]; }
        float inv = 1.0f / se;
        #pragma unroll
        for (int e = 0; e < Ez; e++) { pr[e] *= inv; out_probs[b * Ez + e] = pr[e]; }
        int i0 = 0;
        #pragma unroll
        for (int e = 1; e < Ez; e++) if (pr[e] > pr[i0]) i0 = e;
        int i1 = (i0 == 0) ? 1 : 0;
        #pragma unroll
        for (int e = 0; e < Ez; e++) if (e != i0 && pr[e] > pr[i1]) i1 = e;
        float s2 = pr[i0] + pr[i1];
        if (s2 < 1e-6f) s2 = 1e-6f;
        float inv2 = SCALE / s2;
        #pragma unroll
        for (int e = 0; e < Ez; e++) g_w[b * Ez + e] = 0.f;
        g_w[b * Ez + i0] = pr[i0] * inv2;
        g_w[b * Ez + i1] = pr[i1] * inv2;
    }
}

// ---------------- 3) final: bias + top-2 LoRA combine ----------------
__global__ void final_kernel(const float* __restrict__ b_base,
                             const float* __restrict__ lB,
                             float* __restrict__ out) {
    const int row = blockIdx.x;
    const int t = threadIdx.x;
    const int b = row / Vz;
    __shared__ float temp[Ez * Rz];
    float v = g_acc[row * NCOLS + t];
    if (t >= OUTz) temp[t - OUTz] = v;
    __syncthreads();
    if (t < OUTz) {
        float o = b_base[t] + v;
        #pragma unroll
        for (int e = 0; e < Ez; e++) {
            float w = g_w[b * Ez + e];
            if (w != 0.f) {
                float d = 0.f;
                #pragma unroll
                for (int r = 0; r < Rz; r++)
                    d = fmaf(lB[((size_t)e * OUTz + t) * Rz + r], temp[e * Rz + r], d);
                o = fmaf(w, d, o);
            }
        }
        out[(size_t)row * OUTz + t] = o;
    }
}

// ---------------- launch ----------------
extern "C" void kernel_launch(void* const* d_in, const int* in_sizes, int n_in,
                              void* d_out, int out_size) {
    const float* x   = (const float*)d_in[0];
    const float* Wb  = (const float*)d_in[1];
    const float* bb  = (const float*)d_in[2];
    const float* W1  = (const float*)d_in[3];
    const float* b1v = (const float*)d_in[4];
    const float* W2  = (const float*)d_in[5];
    const float* b2v = (const float*)d_in[6];
    const float* lA  = (const float*)d_in[7];
    const float* lB  = (const float*)d_in[8];
    float* out = (float*)d_out;
    float* out_probs = out + (size_t)NROWS * OUTz;

    cudaFuncSetAttribute(gemm_mma_kernel, cudaFuncAttributeMaxDynamicSharedMemorySize, SM_TOTAL);

    bprep_kernel<<<(NCOLS * (INz / 4) + 255) / 256, 256>>>(Wb, lA);
    gemm_mma_kernel<<<dim3(11, SPLITK), 256, SM_TOTAL>>>(x);
    router_kernel<<<Bz, 256>>>(W1, b1v, W2, b2v, out_probs);
    final_kernel<<<NROWS, NCOLS>>>(bb, lB, out);
    (void)in_sizes; (void)n_in; (void)out_size;
}

// round 8
// speedup vs baseline: 3.6595x; 1.4053x over previous
#include <cuda_runtime.h>
#include <cuda_bf16.h>
#include <cstdint>

#define Bz 32
#define Vz 21
#define Dz 512
#define Pz 64
#define INz 32768
#define OUTz 96
#define Ez 8
#define Rz 8
#define Hz 256
#define NROWS (Bz*Vz)          /* 672 */
#define NCOLS (OUTz + Ez*Rz)   /* 160 */
#define SPLITK 64
#define KC (INz/SPLITK)        /* 512 */
#define SCALE 2.0f

// GEMM tiling
#define MT 64
#define KT 32
#define NSTEP (KC/KT)          /* 16 */
#define AH_OFF 0
#define AL_OFF 5120
#define BH_OFF 10240
#define BL_OFF 23040
#define STAGE  35840
#define SM_TOTAL (2*STAGE)     /* 71680 */

// ---------------- device scratch ----------------
__device__ float g_pooled[Bz*Dz];                  // raw sums (zeroed per launch)
__device__ float g_h[Bz*Hz];                       // router hidden layer
__device__ float g_w[Bz*Ez];
__device__ float g_acc[NROWS*NCOLS];               // gemm accum (zeroed per launch)
__device__ __nv_bfloat16 g_Bh[(size_t)NCOLS*INz];
__device__ __nv_bfloat16 g_Bl[(size_t)NCOLS*INz];

// ---------------- PTX helpers ----------------
__device__ __forceinline__ uint32_t smem_u32(const void* p) {
    uint32_t a;
    asm("{ .reg .u64 t; cvta.to.shared.u64 t, %1; cvt.u32.u64 %0, t; }" : "=r"(a) : "l"(p));
    return a;
}
#define CP16(dst, src)  asm volatile("cp.async.cg.shared.global [%0], [%1], 16;" :: "r"(dst), "l"(src) : "memory")
#define CP_COMMIT()     asm volatile("cp.async.commit_group;" ::: "memory")
#define CP_WAIT0()      asm volatile("cp.async.wait_group 0;" ::: "memory")
#define LDSM4(r0,r1,r2,r3,addr) \
    asm volatile("ldmatrix.sync.aligned.m8n8.x4.shared.b16 {%0,%1,%2,%3}, [%4];" \
        : "=r"(r0),"=r"(r1),"=r"(r2),"=r"(r3) : "r"(addr))
#define MMA(d, a, b0, b1) \
    asm volatile("mma.sync.aligned.m16n8k16.row.col.f32.bf16.bf16.f32 " \
        "{%0,%1,%2,%3},{%4,%5,%6,%7},{%8,%9},{%0,%1,%2,%3};" \
        : "+f"((d)[0]),"+f"((d)[1]),"+f"((d)[2]),"+f"((d)[3]) \
        : "r"((a)[0]),"r"((a)[1]),"r"((a)[2]),"r"((a)[3]), "r"(b0),"r"(b1))

__device__ __forceinline__ void cvt_hilo(float4 f, uint2& h, uint2& l) {
    __nv_bfloat162 h01 = __floats2bfloat162_rn(f.x, f.y);
    __nv_bfloat162 h23 = __floats2bfloat162_rn(f.z, f.w);
    float rx = f.x - __bfloat162float(h01.x);
    float ry = f.y - __bfloat162float(h01.y);
    float rz = f.z - __bfloat162float(h23.x);
    float rw = f.w - __bfloat162float(h23.y);
    __nv_bfloat162 l01 = __floats2bfloat162_rn(rx, ry);
    __nv_bfloat162 l23 = __floats2bfloat162_rn(rz, rw);
    h.x = reinterpret_cast<uint32_t&>(h01);
    h.y = reinterpret_cast<uint32_t&>(h23);
    l.x = reinterpret_cast<uint32_t&>(l01);
    l.y = reinterpret_cast<uint32_t&>(l23);
}

// ---------------- 0) bprep + zero (fused) ----------------
__global__ void bprep_kernel(const float* __restrict__ Wb, const float* __restrict__ lA) {
    int idx = blockIdx.x * 256 + threadIdx.x;
    if (idx < Bz * Dz) g_pooled[idx] = 0.f;
    if (idx < NROWS * NCOLS) g_acc[idx] = 0.f;
    if (idx >= NCOLS * (INz / 4)) return;
    int row = idx / (INz / 4);
    int c   = idx % (INz / 4);
    const float* src = (row < OUTz ? Wb + (size_t)row * INz
                                   : lA + (size_t)(row - OUTz) * INz) + c * 4;
    float4 f = *(const float4*)src;
    uint2 h, l; cvt_hilo(f, h, l);
    ((uint2*)g_Bh)[idx] = h;
    ((uint2*)g_Bl)[idx] = l;
}

// ---------------- 1) fused gemm: MMA + pooled sums + atomic epilogue -------
// grid (11, 64), 256 thr (8 warps: 4 M x 2 N), 2 CTA/SM, ONE sync per stage
__global__ __launch_bounds__(256, 2)
void gemm_mma_kernel(const float* __restrict__ x) {
    extern __shared__ char smem[];
    const uint32_t sb = smem_u32(smem);
    const int t = threadIdx.x;
    const int lane = t & 31;
    const int wid = t >> 5;
    const int wm = wid & 3;
    const int wn = wid >> 2;
    const int m0 = blockIdx.x * MT;
    const int k0 = blockIdx.y * KC;
    const int d0 = k0 >> 6;

    const float* aptr[2]; uint32_t asts[2]; bool aval[2]; int abid[2];
    #pragma unroll
    for (int j = 0; j < 2; j++) {
        int idx = t + j * 256;
        int arow = idx >> 3, ac4 = idx & 7;
        int gr = m0 + arow;
        aval[j] = gr < NROWS;
        abid[j] = (aval[j] ? gr : 0) / Vz;
        aptr[j] = x + (size_t)(aval[j] ? gr : 0) * INz + k0 + ac4 * 4;
        asts[j] = (uint32_t)(arow * 80 + ac4 * 8);
    }
    const __nv_bfloat16* bsrc[5]; uint32_t bsts[5];
    #pragma unroll
    for (int j = 0; j < 5; j++) {
        int idx = t + j * 256;
        int plane = idx >= 640;
        int i2 = idx - plane * 640;
        int brow = i2 >> 2, bc = i2 & 3;
        bsrc[j] = (plane ? g_Bl : g_Bh) + (size_t)brow * INz + k0 + bc * 8;
        bsts[j] = (uint32_t)((plane ? BL_OFF : BH_OFF) + brow * 80 + bc * 16);
    }

    const uint32_t a_lane = (uint32_t)((wm * 16 + (lane & 15)) * 80 + (lane >> 4) * 16);
    const int q = (lane >> 3) & 3;
    const uint32_t b_lane = (uint32_t)(((q >> 1) * 8 + (lane & 7)) * 80 + (q & 1) * 16
                                       + wn * 80 * 80 + BH_OFF);

    float acc[10][4];
    #pragma unroll
    for (int j = 0; j < 10; j++)
        #pragma unroll
        for (int i = 0; i < 4; i++) acc[j][i] = 0.f;

    float4 areg[2];
    #pragma unroll
    for (int j = 0; j < 2; j++)
        areg[j] = aval[j] ? *(const float4*)aptr[j] : make_float4(0.f, 0.f, 0.f, 0.f);
    #pragma unroll
    for (int j = 0; j < 5; j++) CP16(sb + bsts[j], bsrc[j]);
    CP_COMMIT();

    float rsum0 = 0.f, rsum1 = 0.f;

    for (int s = 0; s < NSTEP; s++) {
        const uint32_t base = sb + (uint32_t)(s & 1) * STAGE;
        #pragma unroll
        for (int j = 0; j < 2; j++) {
            uint2 h, l; cvt_hilo(areg[j], h, l);
            *(uint2*)(smem + (base - sb) + AH_OFF + asts[j]) = h;
            *(uint2*)(smem + (base - sb) + AL_OFF + asts[j]) = l;
        }
        rsum0 += (areg[0].x + areg[0].y) + (areg[0].z + areg[0].w);
        rsum1 += (areg[1].x + areg[1].y) + (areg[1].z + areg[1].w);
        if (s & 1) {
            float v0 = rsum0, v1 = rsum1;
            #pragma unroll
            for (int o = 4; o; o >>= 1) {
                v0 += __shfl_down_sync(0xffffffffu, v0, o, 8);
                v1 += __shfl_down_sync(0xffffffffu, v1, o, 8);
            }
            if ((t & 7) == 0) {
                int d = d0 + (s >> 1);
                if (aval[0]) atomicAdd(&g_pooled[abid[0] * Dz + d], v0);
                if (aval[1]) atomicAdd(&g_pooled[abid[1] * Dz + d], v1);
            }
            rsum0 = 0.f; rsum1 = 0.f;
        }
        CP_WAIT0();
        __syncthreads();                      // the ONLY barrier per stage
        if (s + 1 < NSTEP) {
            const int koff = (s + 1) * KT;
            #pragma unroll
            for (int j = 0; j < 2; j++)
                areg[j] = aval[j] ? *(const float4*)(aptr[j] + koff)
                                  : make_float4(0.f, 0.f, 0.f, 0.f);
            const uint32_t nbase = sb + (uint32_t)((s + 1) & 1) * STAGE;
            #pragma unroll
            for (int j = 0; j < 5; j++) CP16(nbase + bsts[j], bsrc[j] + koff);
            CP_COMMIT();
        }
        #pragma unroll
        for (int kk = 0; kk < 2; kk++) {
            uint32_t ah[4], al[4];
            LDSM4(ah[0], ah[1], ah[2], ah[3], base + AH_OFF + a_lane + kk * 32);
            LDSM4(al[0], al[1], al[2], al[3], base + AL_OFF + a_lane + kk * 32);
            uint32_t bh[2][4], bl[2][4];
            {
                const uint32_t ba = base + b_lane + kk * 32;
                LDSM4(bh[0][0], bh[0][1], bh[0][2], bh[0][3], ba);
                LDSM4(bl[0][0], bl[0][1], bl[0][2], bl[0][3], ba + (BL_OFF - BH_OFF));
            }
            #pragma unroll
            for (int jp = 0; jp < 5; jp++) {
                const int cur = jp & 1, nxt = cur ^ 1;
                if (jp < 4) {
                    const uint32_t ba = base + b_lane + (jp + 1) * 1280 + kk * 32;
                    LDSM4(bh[nxt][0], bh[nxt][1], bh[nxt][2], bh[nxt][3], ba);
                    LDSM4(bl[nxt][0], bl[nxt][1], bl[nxt][2], bl[nxt][3], ba + (BL_OFF - BH_OFF));
                }
                float* a0 = acc[jp * 2 + 0];
                float* a1 = acc[jp * 2 + 1];
                MMA(a0, ah, bh[cur][0], bh[cur][1]);
                MMA(a1, ah, bh[cur][2], bh[cur][3]);
                MMA(a0, ah, bl[cur][0], bl[cur][1]);
                MMA(a1, ah, bl[cur][2], bl[cur][3]);
                MMA(a0, al, bh[cur][0], bh[cur][1]);
                MMA(a1, al, bh[cur][2], bh[cur][3]);
            }
        }
        // no trailing sync: STS(s+2) into this buffer is ordered after sync(s+1),
        // which every warp passes only after finishing compute(s) here.
    }

    const int r0 = m0 + wm * 16 + (lane >> 2);
    const int c0 = wn * 80 + (lane & 3) * 2;
    #pragma unroll
    for (int j = 0; j < 10; j++) {
        int col = c0 + j * 8;
        if (r0 < NROWS) {
            atomicAdd(&g_acc[r0 * NCOLS + col],     acc[j][0]);
            atomicAdd(&g_acc[r0 * NCOLS + col + 1], acc[j][1]);
        }
        if (r0 + 8 < NROWS) {
            atomicAdd(&g_acc[(r0 + 8) * NCOLS + col],     acc[j][2]);
            atomicAdd(&g_acc[(r0 + 8) * NCOLS + col + 1], acc[j][3]);
        }
    }
}

// ---------------- 2a) router hidden layer: grid (Bz, Hz/32), warp-per-row ----
__global__ void router_h_kernel(const float* __restrict__ W1, const float* __restrict__ b1) {
    __shared__ float sp[Dz];
    const float invVP = 1.0f / (Vz * Pz);
    const int b = blockIdx.x;
    const int chunk = blockIdx.y;          // 0..7, covers rows chunk*32..+31
    const int t = threadIdx.x;             // 256 threads = 8 warps
    const int warp = t >> 5, lane = t & 31;
    for (int i = t; i < Dz; i += 256) sp[i] = g_pooled[b * Dz + i] * invVP;
    __syncthreads();
    #pragma unroll
    for (int rr = 0; rr < 4; rr++) {       // 8 warps x 4 rows = 32 rows
        int r = chunk * 32 + warp * 4 + rr;
        const float* w = W1 + (size_t)r * Dz;
        float acc = 0.f;
        #pragma unroll
        for (int k = 0; k < Dz / 32; k++) acc = fmaf(sp[k * 32 + lane], w[k * 32 + lane], acc);
        #pragma unroll
        for (int o = 16; o; o >>= 1) acc += __shfl_xor_sync(0xffffffffu, acc, o);
        if (lane == 0) g_h[b * Hz + r] = fmaxf(acc + b1[r], 0.f);
    }
}

// ---------------- 2b) router logits + softmax + top-2 ----------------
__global__ void router_top_kernel(const float* __restrict__ W2, const float* __restrict__ b2,
                                  float* __restrict__ out_probs) {
    __shared__ float sh[Hz];
    __shared__ float sl[Ez];
    const int b = blockIdx.x, t = threadIdx.x;
    const int warp = t >> 5, lane = t & 31;
    for (int i = t; i < Hz; i += 256) sh[i] = g_h[b * Hz + i];
    __syncthreads();
    if (warp < Ez) {
        const float* w = W2 + (size_t)warp * Hz;
        float acc = 0.f;
        #pragma unroll
        for (int k = 0; k < Hz / 32; k++) acc = fmaf(sh[k * 32 + lane], w[k * 32 + lane], acc);
        #pragma unroll
        for (int o = 16; o; o >>= 1) acc += __shfl_xor_sync(0xffffffffu, acc, o);
        if (lane == 0) sl[warp] = acc + b2[warp];
    }
    __syncthreads();
    if (t == 0) {
        float mx = -1e30f;
        #pragma unroll
        for (int e = 0; e < Ez; e++) mx = fmaxf(mx, sl[e]);
        float pr[Ez]; float se = 0.f;
        #pragma unroll
        for (int e = 0; e < Ez; e++) { pr[e] = expf(sl[e] - mx); se += pr[e]; }
        float inv = 1.0f / se;
        #pragma unroll
        for (int e = 0; e < Ez; e++) { pr[e] *= inv; out_probs[b * Ez + e] = pr[e]; }
        int i0 = 0;
        #pragma unroll
        for (int e = 1; e < Ez; e++) if (pr[e] > pr[i0]) i0 = e;
        int i1 = (i0 == 0) ? 1 : 0;
        #pragma unroll
        for (int e = 0; e < Ez; e++) if (e != i0 && pr[e] > pr[i1]) i1 = e;
        float s2 = pr[i0] + pr[i1];
        if (s2 < 1e-6f) s2 = 1e-6f;
        float inv2 = SCALE / s2;
        #pragma unroll
        for (int e = 0; e < Ez; e++) g_w[b * Ez + e] = 0.f;
        g_w[b * Ez + i0] = pr[i0] * inv2;
        g_w[b * Ez + i1] = pr[i1] * inv2;
    }
}

// ---------------- 3) final: bias + top-2 LoRA combine ----------------
__global__ void final_kernel(const float* __restrict__ b_base,
                             const float* __restrict__ lB,
                             float* __restrict__ out) {
    const int row = blockIdx.x;
    const int t = threadIdx.x;
    const int b = row / Vz;
    __shared__ float temp[Ez * Rz];
    float v = g_acc[row * NCOLS + t];
    if (t >= OUTz) temp[t - OUTz] = v;
    __syncthreads();
    if (t < OUTz) {
        float o = b_base[t] + v;
        #pragma unroll
        for (int e = 0; e < Ez; e++) {
            float w = g_w[b * Ez + e];
            if (w != 0.f) {
                float d = 0.f;
                #pragma unroll
                for (int r = 0; r < Rz; r++)
                    d = fmaf(lB[((size_t)e * OUTz + t) * Rz + r], temp[e * Rz + r], d);
                o = fmaf(w, d, o);
            }
        }
        out[(size_t)row * OUTz + t] = o;
    }
}

// ---------------- launch ----------------
extern "C" void kernel_launch(void* const* d_in, const int* in_sizes, int n_in,
                              void* d_out, int out_size) {
    const float* x   = (const float*)d_in[0];
    const float* Wb  = (const float*)d_in[1];
    const float* bb  = (const float*)d_in[2];
    const float* W1  = (const float*)d_in[3];
    const float* b1v = (const float*)d_in[4];
    const float* W2  = (const float*)d_in[5];
    const float* b2v = (const float*)d_in[6];
    const float* lA  = (const float*)d_in[7];
    const float* lB  = (const float*)d_in[8];
    float* out = (float*)d_out;
    float* out_probs = out + (size_t)NROWS * OUTz;

    cudaFuncSetAttribute(gemm_mma_kernel, cudaFuncAttributeMaxDynamicSharedMemorySize, SM_TOTAL);

    bprep_kernel<<<(NCOLS * (INz / 4) + 255) / 256, 256>>>(Wb, lA);
    gemm_mma_kernel<<<dim3(11, SPLITK), 256, SM_TOTAL>>>(x);
    router_h_kernel<<<dim3(Bz, Hz / 32), 256>>>(W1, b1v);
    router_top_kernel<<<Bz, 256>>>(W2, b2v, out_probs);
    final_kernel<<<NROWS, NCOLS>>>(bb, lB, out);
    (void)in_sizes; (void)n_in; (void)out_size;
}

// round 9
// speedup vs baseline: 3.8991x; 1.0655x over previous
#include <cuda_runtime.h>
#include <cuda_bf16.h>
#include <cstdint>

#define Bz 32
#define Vz 21
#define Dz 512
#define Pz 64
#define INz 32768
#define OUTz 96
#define Ez 8
#define Rz 8
#define Hz 256
#define NROWS (Bz*Vz)          /* 672 */
#define NCOLS (OUTz + Ez*Rz)   /* 160 */
#define SPLITK 64
#define KC (INz/SPLITK)        /* 512 */
#define SCALE 2.0f

// GEMM tiling
#define MT 64
#define KT 32
#define NSTEP (KC/KT)          /* 16 */
#define AH_OFF 0
#define AL_OFF 5120
#define BH_OFF 10240
#define BL_OFF 23040
#define STAGE  35840
#define SM_TOTAL (2*STAGE)     /* 71680 */

// ---------------- device scratch ----------------
__device__ float g_pooled[Bz*Dz];
__device__ float g_h[Bz*Hz];
__device__ float g_acc[NROWS*NCOLS];
__device__ __nv_bfloat16 g_Bh[(size_t)NCOLS*INz];
__device__ __nv_bfloat16 g_Bl[(size_t)NCOLS*INz];

// ---------------- PTX helpers ----------------
__device__ __forceinline__ uint32_t smem_u32(const void* p) {
    uint32_t a;
    asm("{ .reg .u64 t; cvta.to.shared.u64 t, %1; cvt.u32.u64 %0, t; }" : "=r"(a) : "l"(p));
    return a;
}
#define CP16(dst, src)  asm volatile("cp.async.cg.shared.global [%0], [%1], 16;" :: "r"(dst), "l"(src) : "memory")
#define CP_COMMIT()     asm volatile("cp.async.commit_group;" ::: "memory")
#define CP_WAIT0()      asm volatile("cp.async.wait_group 0;" ::: "memory")
#define LDSM4(r0,r1,r2,r3,addr) \
    asm volatile("ldmatrix.sync.aligned.m8n8.x4.shared.b16 {%0,%1,%2,%3}, [%4];" \
        : "=r"(r0),"=r"(r1),"=r"(r2),"=r"(r3) : "r"(addr))
#define LDSM2(r0,r1,addr) \
    asm volatile("ldmatrix.sync.aligned.m8n8.x2.shared.b16 {%0,%1}, [%2];" \
        : "=r"(r0),"=r"(r1) : "r"(addr))
#define MMA(d, a, b0, b1) \
    asm volatile("mma.sync.aligned.m16n8k16.row.col.f32.bf16.bf16.f32 " \
        "{%0,%1,%2,%3},{%4,%5,%6,%7},{%8,%9},{%0,%1,%2,%3};" \
        : "+f"((d)[0]),"+f"((d)[1]),"+f"((d)[2]),"+f"((d)[3]) \
        : "r"((a)[0]),"r"((a)[1]),"r"((a)[2]),"r"((a)[3]), "r"(b0),"r"(b1))

__device__ __forceinline__ void cvt_hilo(float4 f, uint2& h, uint2& l) {
    __nv_bfloat162 h01 = __floats2bfloat162_rn(f.x, f.y);
    __nv_bfloat162 h23 = __floats2bfloat162_rn(f.z, f.w);
    float rx = f.x - __bfloat162float(h01.x);
    float ry = f.y - __bfloat162float(h01.y);
    float rz = f.z - __bfloat162float(h23.x);
    float rw = f.w - __bfloat162float(h23.y);
    __nv_bfloat162 l01 = __floats2bfloat162_rn(rx, ry);
    __nv_bfloat162 l23 = __floats2bfloat162_rn(rz, rw);
    h.x = reinterpret_cast<uint32_t&>(h01);
    h.y = reinterpret_cast<uint32_t&>(h23);
    l.x = reinterpret_cast<uint32_t&>(l01);
    l.y = reinterpret_cast<uint32_t&>(l23);
}

// ---------------- 0) bprep + zero (fused) ----------------
__global__ void bprep_kernel(const float* __restrict__ Wb, const float* __restrict__ lA) {
    int idx = blockIdx.x * 256 + threadIdx.x;
    if (idx < Bz * Dz) g_pooled[idx] = 0.f;
    if (idx < NROWS * NCOLS) g_acc[idx] = 0.f;
    if (idx >= NCOLS * (INz / 4)) return;
    int row = idx / (INz / 4);
    int c   = idx % (INz / 4);
    const float* src = (row < OUTz ? Wb + (size_t)row * INz
                                   : lA + (size_t)(row - OUTz) * INz) + c * 4;
    float4 f = *(const float4*)src;
    uint2 h, l; cvt_hilo(f, h, l);
    ((uint2*)g_Bh)[idx] = h;
    ((uint2*)g_Bl)[idx] = l;
}

// ---------------- 1) fused gemm: MMA + pooled sums + atomic epilogue -------
// grid (11, 64), 256 thr. Warp layout (2M x 4N): warp owns 32 M-rows x 40 N-cols.
__global__ __launch_bounds__(256, 2)
void gemm_mma_kernel(const float* __restrict__ x) {
    extern __shared__ char smem[];
    const uint32_t sb = smem_u32(smem);
    const int t = threadIdx.x;
    const int lane = t & 31;
    const int wid = t >> 5;
    const int wm = wid & 1;          // 2 M-groups of 32 rows
    const int wn = wid >> 1;         // 4 N-groups of 40 cols
    const int m0 = blockIdx.x * MT;
    const int k0 = blockIdx.y * KC;
    const int d0 = k0 >> 6;

    // A loader (unchanged): 2 float4 per thread per stage
    const float* aptr[2]; uint32_t asts[2]; bool aval[2]; int abid[2];
    #pragma unroll
    for (int j = 0; j < 2; j++) {
        int idx = t + j * 256;
        int arow = idx >> 3, ac4 = idx & 7;
        int gr = m0 + arow;
        aval[j] = gr < NROWS;
        abid[j] = (aval[j] ? gr : 0) / Vz;
        aptr[j] = x + (size_t)(aval[j] ? gr : 0) * INz + k0 + ac4 * 4;
        asts[j] = (uint32_t)(arow * 80 + ac4 * 8);
    }
    // B loader (unchanged): 5 x 16B cp.async per thread per stage
    const __nv_bfloat16* bsrc[5]; uint32_t bsts[5];
    #pragma unroll
    for (int j = 0; j < 5; j++) {
        int idx = t + j * 256;
        int plane = idx >= 640;
        int i2 = idx - plane * 640;
        int brow = i2 >> 2, bc = i2 & 3;
        bsrc[j] = (plane ? g_Bl : g_Bh) + (size_t)brow * INz + k0 + bc * 8;
        bsts[j] = (uint32_t)((plane ? BL_OFF : BH_OFF) + brow * 80 + bc * 16);
    }

    // ldmatrix lane addresses
    const uint32_t a_lane = (uint32_t)((wm * 32 + (lane & 15)) * 80 + (lane >> 4) * 16);
    const int q = (lane >> 3) & 3;
    const uint32_t b_lane4 = (uint32_t)(wn * 3200 + ((q >> 1) * 8 + (lane & 7)) * 80
                                        + (q & 1) * 16 + BH_OFF);
    const uint32_t b_lane2 = (uint32_t)(wn * 3200 + (32 + (lane & 7)) * 80
                                        + ((lane >> 3) & 1) * 16 + BH_OFF);

    float acc[2][5][4];
    #pragma unroll
    for (int mt = 0; mt < 2; mt++)
        #pragma unroll
        for (int nt = 0; nt < 5; nt++)
            #pragma unroll
            for (int i = 0; i < 4; i++) acc[mt][nt][i] = 0.f;

    float4 areg[2];
    #pragma unroll
    for (int j = 0; j < 2; j++)
        areg[j] = aval[j] ? *(const float4*)aptr[j] : make_float4(0.f, 0.f, 0.f, 0.f);
    #pragma unroll
    for (int j = 0; j < 5; j++) CP16(sb + bsts[j], bsrc[j]);
    CP_COMMIT();

    float rsum0 = 0.f, rsum1 = 0.f;

    for (int s = 0; s < NSTEP; s++) {
        const uint32_t base = sb + (uint32_t)(s & 1) * STAGE;
        #pragma unroll
        for (int j = 0; j < 2; j++) {
            uint2 h, l; cvt_hilo(areg[j], h, l);
            *(uint2*)(smem + (base - sb) + AH_OFF + asts[j]) = h;
            *(uint2*)(smem + (base - sb) + AL_OFF + asts[j]) = l;
        }
        rsum0 += (areg[0].x + areg[0].y) + (areg[0].z + areg[0].w);
        rsum1 += (areg[1].x + areg[1].y) + (areg[1].z + areg[1].w);
        if (s & 1) {
            float v0 = rsum0, v1 = rsum1;
            #pragma unroll
            for (int o = 4; o; o >>= 1) {
                v0 += __shfl_down_sync(0xffffffffu, v0, o, 8);
                v1 += __shfl_down_sync(0xffffffffu, v1, o, 8);
            }
            if ((t & 7) == 0) {
                int d = d0 + (s >> 1);
                if (aval[0]) atomicAdd(&g_pooled[abid[0] * Dz + d], v0);
                if (aval[1]) atomicAdd(&g_pooled[abid[1] * Dz + d], v1);
            }
            rsum0 = 0.f; rsum1 = 0.f;
        }
        CP_WAIT0();
        __syncthreads();                      // the only barrier per stage
        if (s + 1 < NSTEP) {
            const int koff = (s + 1) * KT;
            #pragma unroll
            for (int j = 0; j < 2; j++)
                areg[j] = aval[j] ? *(const float4*)(aptr[j] + koff)
                                  : make_float4(0.f, 0.f, 0.f, 0.f);
            const uint32_t nbase = sb + (uint32_t)((s + 1) & 1) * STAGE;
            #pragma unroll
            for (int j = 0; j < 5; j++) CP16(nbase + bsts[j], bsrc[j] + koff);
            CP_COMMIT();
        }
        #pragma unroll
        for (int kk = 0; kk < 2; kk++) {
            uint32_t ah[2][4], al[2][4];
            LDSM4(ah[0][0], ah[0][1], ah[0][2], ah[0][3], base + AH_OFF + a_lane + kk * 32);
            LDSM4(ah[1][0], ah[1][1], ah[1][2], ah[1][3], base + AH_OFF + a_lane + 1280 + kk * 32);
            LDSM4(al[0][0], al[0][1], al[0][2], al[0][3], base + AL_OFF + a_lane + kk * 32);
            LDSM4(al[1][0], al[1][1], al[1][2], al[1][3], base + AL_OFF + a_lane + 1280 + kk * 32);
            uint32_t bh[10], bl[10];
            {
                const uint32_t ba = base + b_lane4 + kk * 32;
                LDSM4(bh[0], bh[1], bh[2], bh[3], ba);
                LDSM4(bh[4], bh[5], bh[6], bh[7], ba + 16 * 80);
                LDSM2(bh[8], bh[9], base + b_lane2 + kk * 32);
                const uint32_t bd = BL_OFF - BH_OFF;
                LDSM4(bl[0], bl[1], bl[2], bl[3], ba + bd);
                LDSM4(bl[4], bl[5], bl[6], bl[7], ba + 16 * 80 + bd);
                LDSM2(bl[8], bl[9], base + b_lane2 + kk * 32 + bd);
            }
            #pragma unroll
            for (int nt = 0; nt < 5; nt++) {
                uint32_t b0h = bh[nt * 2], b1h = bh[nt * 2 + 1];
                uint32_t b0l = bl[nt * 2], b1l = bl[nt * 2 + 1];
                MMA(acc[0][nt], ah[0], b0h, b1h);
                MMA(acc[1][nt], ah[1], b0h, b1h);
                MMA(acc[0][nt], ah[0], b0l, b1l);
                MMA(acc[1][nt], ah[1], b0l, b1l);
                MMA(acc[0][nt], al[0], b0h, b1h);
                MMA(acc[1][nt], al[1], b0h, b1h);
            }
        }
    }

    // epilogue: atomic-reduce into g_acc
    #pragma unroll
    for (int mt = 0; mt < 2; mt++) {
        const int r0 = m0 + wm * 32 + mt * 16 + (lane >> 2);
        #pragma unroll
        for (int nt = 0; nt < 5; nt++) {
            const int col = wn * 40 + nt * 8 + (lane & 3) * 2;
            if (r0 < NROWS) {
                atomicAdd(&g_acc[r0 * NCOLS + col],     acc[mt][nt][0]);
                atomicAdd(&g_acc[r0 * NCOLS + col + 1], acc[mt][nt][1]);
            }
            if (r0 + 8 < NROWS) {
                atomicAdd(&g_acc[(r0 + 8) * NCOLS + col],     acc[mt][nt][2]);
                atomicAdd(&g_acc[(r0 + 8) * NCOLS + col + 1], acc[mt][nt][3]);
            }
        }
    }
}

// ---------------- 2) router hidden layer: grid (Bz, Hz/32), warp-per-row ----
__global__ void router_h_kernel(const float* __restrict__ W1, const float* __restrict__ b1) {
    __shared__ float sp[Dz];
    const float invVP = 1.0f / (Vz * Pz);
    const int b = blockIdx.x;
    const int chunk = blockIdx.y;
    const int t = threadIdx.x;
    const int warp = t >> 5, lane = t & 31;
    for (int i = t; i < Dz; i += 256) sp[i] = g_pooled[b * Dz + i] * invVP;
    __syncthreads();
    #pragma unroll
    for (int rr = 0; rr < 4; rr++) {
        int r = chunk * 32 + warp * 4 + rr;
        const float* w = W1 + (size_t)r * Dz;
        float acc = 0.f;
        #pragma unroll
        for (int k = 0; k < Dz / 32; k++) acc = fmaf(sp[k * 32 + lane], w[k * 32 + lane], acc);
        #pragma unroll
        for (int o = 16; o; o >>= 1) acc += __shfl_xor_sync(0xffffffffu, acc, o);
        if (lane == 0) g_h[b * Hz + r] = fmaxf(acc + b1[r], 0.f);
    }
}

// ---------------- 3) final: logits + softmax + top-2 + bias + LoRA combine --
__global__ __launch_bounds__(256)
void final_kernel(const float* __restrict__ W2, const float* __restrict__ b2,
                  const float* __restrict__ b_base, const float* __restrict__ lB,
                  float* __restrict__ out, float* __restrict__ out_probs) {
    const int row = blockIdx.x;
    const int t = threadIdx.x;
    const int b = row / Vz;
    const int warp = t >> 5, lane = t & 31;
    __shared__ float sh[Hz];
    __shared__ float sl[Ez];
    __shared__ float sw[Ez];
    __shared__ float temp[Ez * Rz];
    sh[t] = g_h[b * Hz + t];
    float v = 0.f;
    if (t < NCOLS) {
        v = g_acc[row * NCOLS + t];
        if (t >= OUTz) temp[t - OUTz] = v;
    }
    __syncthreads();
    if (warp < Ez) {
        const float* w = W2 + (size_t)warp * Hz;
        float acc = 0.f;
        #pragma unroll
        for (int k = 0; k < Hz / 32; k++) acc = fmaf(sh[k * 32 + lane], w[k * 32 + lane], acc);
        #pragma unroll
        for (int o = 16; o; o >>= 1) acc += __shfl_xor_sync(0xffffffffu, acc, o);
        if (lane == 0) sl[warp] = acc + b2[warp];
    }
    __syncthreads();
    if (t == 0) {
        float mx = -1e30f;
        #pragma unroll
        for (int e = 0; e < Ez; e++) mx = fmaxf(mx, sl[e]);
        float pr[Ez]; float se = 0.f;
        #pragma unroll
        for (int e = 0; e < Ez; e++) { pr[e] = expf(sl[e] - mx); se += pr[e]; }
        float inv = 1.0f / se;
        #pragma unroll
        for (int e = 0; e < Ez; e++) pr[e] *= inv;
        if (row % Vz == 0) {
            #pragma unroll
            for (int e = 0; e < Ez; e++) out_probs[b * Ez + e] = pr[e];
        }
        int i0 = 0;
        #pragma unroll
        for (int e = 1; e < Ez; e++) if (pr[e] > pr[i0]) i0 = e;
        int i1 = (i0 == 0) ? 1 : 0;
        #pragma unroll
        for (int e = 0; e < Ez; e++) if (e != i0 && pr[e] > pr[i1]) i1 = e;
        float s2 = pr[i0] + pr[i1];
        if (s2 < 1e-6f) s2 = 1e-6f;
        float inv2 = SCALE / s2;
        #pragma unroll
        for (int e = 0; e < Ez; e++) sw[e] = 0.f;
        sw[i0] = pr[i0] * inv2;
        sw[i1] = pr[i1] * inv2;
    }
    __syncthreads();
    if (t < OUTz) {
        float o = b_base[t] + v;
        #pragma unroll
        for (int e = 0; e < Ez; e++) {
            float w = sw[e];
            if (w != 0.f) {
                float d = 0.f;
                #pragma unroll
                for (int r = 0; r < Rz; r++)
                    d = fmaf(lB[((size_t)e * OUTz + t) * Rz + r], temp[e * Rz + r], d);
                o = fmaf(w, d, o);
            }
        }
        out[(size_t)row * OUTz + t] = o;
    }
}

// ---------------- launch ----------------
extern "C" void kernel_launch(void* const* d_in, const int* in_sizes, int n_in,
                              void* d_out, int out_size) {
    const float* x   = (const float*)d_in[0];
    const float* Wb  = (const float*)d_in[1];
    const float* bb  = (const float*)d_in[2];
    const float* W1  = (const float*)d_in[3];
    const float* b1v = (const float*)d_in[4];
    const float* W2  = (const float*)d_in[5];
    const float* b2v = (const float*)d_in[6];
    const float* lA  = (const float*)d_in[7];
    const float* lB  = (const float*)d_in[8];
    float* out = (float*)d_out;
    float* out_probs = out + (size_t)NROWS * OUTz;

    cudaFuncSetAttribute(gemm_mma_kernel, cudaFuncAttributeMaxDynamicSharedMemorySize, SM_TOTAL);

    bprep_kernel<<<(NCOLS * (INz / 4) + 255) / 256, 256>>>(Wb, lA);
    gemm_mma_kernel<<<dim3(11, SPLITK), 256, SM_TOTAL>>>(x);
    router_h_kernel<<<dim3(Bz, Hz / 32), 256>>>(W1, b1v);
    final_kernel<<<NROWS, 256>>>(W2, b2v, bb, lB, out, out_probs);
    (void)in_sizes; (void)n_in; (void)out_size;
}